// round 8
// baseline (speedup 1.0000x reference)
#include <cuda_runtime.h>
#include <math.h>

#define BB     256
#define MEMN   70
#define SLENQ  11
#define LQ     71
#define BL     (BB*LQ)       // 18176
#define HD     512
#define FSZ    2048
#define NHEAD  8
#define DKH    64
#define NLMAX  6
#define VOC    32000
#define QKVN   1536
#define THRESHV 0.9f
#define EPSV   1e-6f

// smem stage sizes (floats)
#define ASZ2 (256*36)
#define BSZ  (32*136)
#define ASZ1 (128*36)
#define BSZ_NT (128*36)
#define SMEM_NN (3*(ASZ2+BSZ)*4)       // 162816 B
#define SMEM_NT (3*(ASZ1+BSZ_NT)*4)    // 110592 B

// ---------------- scratch (device globals; no allocation) ----------------
__device__ float g_x[BL*HD];
__device__ float g_state[BL*HD];
__device__ float g_prev[BL*HD];
__device__ float g_s[BL*HD];
__device__ float g_xn[BL*HD];
__device__ float g_qkv[BL*QKVN];
__device__ float g_ctx[BL*HD];
__device__ float g_s2[BL*HD];
__device__ float g_xn2[BL*HD];
__device__ float g_y[BL*HD];
__device__ float g_mid[BL*FSZ];
__device__ float g_w1t[3*HD*FSZ];        // [3*512][2048]  (tf32-rounded)
__device__ float g_w2t[3*FSZ*HD];        // [3*2048][512]  (tf32-rounded)
__device__ float g_wr[5*HD*HD];          // rounded projw,-,-,-,wo
__device__ float g_wqkv[HD*QKVN];        // rounded [512][1536] = 0.125*wq | wk | wv
__device__ float g_embr[VOC*HD];         // rounded emb
__device__ float g_tsig[LQ*HD];
__device__ float g_psig[NLMAX*HD];
__device__ float g_hp[BL], g_rem[BL], g_nu[BL], g_pr[BL];
__device__ float g_pooled[BB*HD];
__device__ int   g_active;

// ---------------- helpers ----------------
__device__ __forceinline__ float roundtf(float f) {
    unsigned u;
    asm("cvt.rna.tf32.f32 %0, %1;" : "=r"(u) : "f"(f));
    return __uint_as_float(u);
}

__device__ __forceinline__ void mma_tf32(float* d, const unsigned* a, const unsigned* b) {
    asm volatile(
        "mma.sync.aligned.m16n8k8.row.col.f32.tf32.tf32.f32 "
        "{%0,%1,%2,%3}, {%4,%5,%6,%7}, {%8,%9}, {%0,%1,%2,%3};"
        : "+f"(d[0]), "+f"(d[1]), "+f"(d[2]), "+f"(d[3])
        : "r"(a[0]), "r"(a[1]), "r"(a[2]), "r"(a[3]), "r"(b[0]), "r"(b[1]));
}

__device__ __forceinline__ void cp16(void* dst, const void* src, int ss) {
    unsigned d = (unsigned)__cvta_generic_to_shared(dst);
    asm volatile("cp.async.cg.shared.global [%0], [%1], 16, %2;"
                 :: "r"(d), "l"(src), "r"(ss));
}
__device__ __forceinline__ void cp_commit() {
    asm volatile("cp.async.commit_group;");
}
__device__ __forceinline__ void cp_wait1() {
    asm volatile("cp.async.wait_group 1;");
}

__device__ __forceinline__ float blockReduceSum(float v) {
    __shared__ float sh[32];
    __shared__ float res;
    int lane = threadIdx.x & 31, wid = threadIdx.x >> 5;
#pragma unroll
    for (int o = 16; o; o >>= 1) v += __shfl_xor_sync(0xffffffffu, v, o);
    if (lane == 0) sh[wid] = v;
    __syncthreads();
    if (wid == 0) {
        float x = (lane < (int)(blockDim.x >> 5)) ? sh[lane] : 0.f;
#pragma unroll
        for (int o = 16; o; o >>= 1) x += __shfl_xor_sync(0xffffffffu, x, o);
        if (lane == 0) res = x;
    }
    __syncthreads();
    return res;
}

__device__ __forceinline__ float blockReduceMax(float v) {
    __shared__ float sh[32];
    __shared__ float res;
    int lane = threadIdx.x & 31, wid = threadIdx.x >> 5;
#pragma unroll
    for (int o = 16; o; o >>= 1) v = fmaxf(v, __shfl_xor_sync(0xffffffffu, v, o));
    if (lane == 0) sh[wid] = v;
    __syncthreads();
    if (wid == 0) {
        float x = (lane < (int)(blockDim.x >> 5)) ? sh[lane] : -3.0e38f;
#pragma unroll
        for (int o = 16; o; o >>= 1) x = fmaxf(x, __shfl_xor_sync(0xffffffffu, x, o));
        if (lane == 0) res = x;
    }
    __syncthreads();
    return res;
}

// ---------------- init / signals / weight prep ----------------
__global__ void k_init() {
    int i = blockIdx.x * blockDim.x + threadIdx.x;
    if (i < BL*HD) g_prev[i] = 0.f;
    if (i < BL) { g_hp[i] = 0.f; g_rem[i] = 0.f; g_nu[i] = 0.f; }
}

__global__ void k_sigs() {
    int i = blockIdx.x * blockDim.x + threadIdx.x;
    const float log_inc = logf(1e4f) / 255.f;
    if (i < LQ*HD) {
        int pos = i / HD, c = i % HD;
        int j = (c < 256) ? c : c - 256;
        float val = (float)pos * expf(-log_inc * (float)j);
        g_tsig[i] = (c < 256) ? sinf(val) : cosf(val);
    } else {
        int k = i - LQ*HD;
        if (k < NLMAX*HD) {
            int pos = k / HD, c = k % HD;
            int j = (c < 256) ? c : c - 256;
            float val = (float)pos * expf(-log_inc * (float)j);
            g_psig[k] = (c < 256) ? sinf(val) : cosf(val);
        }
    }
}

__global__ void k_wt1(const float* __restrict__ w) {
    int i = blockIdx.x * blockDim.x + threadIdx.x;
    if (i < 3*HD*FSZ) {
        int f = i % FSZ;
        int rest = i / FSZ;
        int kk = rest / HD, c = rest % HD;
        g_w1t[i] = roundtf(w[(f*HD + c)*3 + kk]);
    }
}

__global__ void k_wt2(const float* __restrict__ w) {
    int i = blockIdx.x * blockDim.x + threadIdx.x;
    if (i < 3*FSZ*HD) {
        int f = i % HD;
        int rest = i / HD;
        int kk = rest / FSZ, c = rest % FSZ;
        g_w2t[i] = roundtf(w[(f*FSZ + c)*3 + kk]);
    }
}

__global__ void k_roundw(const float* __restrict__ projw, const float* __restrict__ wo) {
    int i = blockIdx.x * blockDim.x + threadIdx.x;
    if (i < HD*HD) {
        g_wr[0*HD*HD + i] = roundtf(projw[i]);
        g_wr[4*HD*HD + i] = roundtf(wo[i]);
    }
}

__global__ void k_wqkv(const float* __restrict__ wq, const float* __restrict__ wk,
                       const float* __restrict__ wv) {
    int i = blockIdx.x * blockDim.x + threadIdx.x;
    if (i < HD*QKVN) {
        int k = i / QKVN, n = i % QKVN;
        float v;
        if (n < 512)       v = 0.125f * wq[k*HD + n];
        else if (n < 1024) v = wk[k*HD + n - 512];
        else               v = wv[k*HD + n - 1024];
        g_wqkv[i] = roundtf(v);
    }
}

__global__ void k_rounde(const float* __restrict__ emb) {
    long i = (long)blockIdx.x * blockDim.x + threadIdx.x;
    if (i < (long)VOC*HD) g_embr[i] = roundtf(emb[i]);
}

// ---------------- embedding (output rounded: feeds proj GEMM) ----------------
__global__ void k_embed(const int* __restrict__ story, const int* __restrict__ query,
                        const float* __restrict__ emb, const float* __restrict__ mask) {
    int row = blockIdx.x;
    int b = row / LQ, m = row % LQ;
    for (int c = threadIdx.x; c < HD; c += blockDim.x) {
        float acc = 0.f;
        if (m < MEMN) {
#pragma unroll
            for (int s = 0; s < SLENQ; s++) {
                int tok = story[(b*MEMN + m)*SLENQ + s];
                acc += emb[(long)tok*HD + c] * mask[s*HD + c];
            }
        } else {
#pragma unroll
            for (int s = 0; s < SLENQ; s++) {
                int tok = query[b*SLENQ + s];
                acc += emb[(long)tok*HD + c] * mask[s*HD + c];
            }
        }
        g_x[row*HD + c] = roundtf(acc);
    }
}

// ============ tf32 GEMM, 256x128 tile, cp.async 3-stage (NN + conv-im2col) ============
// C = act(A@W + bias + resid); operands MUST be pre-rounded to tf32.
__global__ void __launch_bounds__(256, 1)
k_gemm_tc(const float* __restrict__ A, const float* __restrict__ W,
          float* __restrict__ C, int M, int N, int K,
          const float* __restrict__ bias, const float* __restrict__ resid,
          int relu, int chk, int conv, int Cin, int cshift, int rnd) {
    if (chk && !g_active) return;
    extern __shared__ float smem[];
    float* AsF = smem;                   // [3][256][36]
    float* BsF = smem + 3*ASZ2;          // [3][32][136]

    const int tid = threadIdx.x;
    const int m0 = blockIdx.y * 256;
    const int n0 = blockIdx.x * 128;
    const int lane = tid & 31, wid = tid >> 5;
    const int wm = wid & 3, wn = wid >> 2;   // 4 x 2 warp grid, warp tile 64x64
    const int g = lane >> 2, t = lane & 3;

    float acc[4][8][4];
#pragma unroll
    for (int mi = 0; mi < 4; mi++)
#pragma unroll
        for (int ni = 0; ni < 8; ni++)
#pragma unroll
            for (int j = 0; j < 4; j++) acc[mi][ni][j] = 0.f;

    const int ar = tid >> 3;            // 0..31
    const int ac4 = (tid & 7) * 4;      // 0,4,..,28
    const int br = tid >> 5;            // 0..7
    const int bc4 = (tid & 31) * 4;     // 0..124
    const int NP = K / 32;

    auto loadP = [&](int k0, int buf) {
        float* As = AsF + buf*ASZ2;
        float* Bs = BsF + buf*BSZ;
        if (conv) {
            int kk = k0 >> cshift;
            int cb = k0 & (Cin - 1);
#pragma unroll
            for (int i = 0; i < 8; i++) {
                int m = m0 + ar + i*32;
                int b = m / LQ, l = m - b*LQ;
                int lp = l + kk - 1;
                int ok = (lp >= 0 && lp < LQ);
                const float* src = &A[(long)(b*LQ + (ok ? lp : 0))*Cin + cb + ac4];
                cp16(&As[(ar + i*32)*36 + ac4], src, ok ? 16 : 0);
            }
        } else {
#pragma unroll
            for (int i = 0; i < 8; i++)
                cp16(&As[(ar + i*32)*36 + ac4],
                     &A[(long)(m0 + ar + i*32)*K + k0 + ac4], 16);
        }
#pragma unroll
        for (int i = 0; i < 4; i++)
            cp16(&Bs[(br + i*8)*136 + bc4],
                 &W[(long)(k0 + br + i*8)*N + n0 + bc4], 16);
    };

    auto compute = [&](int buf) {
        const unsigned* As = (const unsigned*)(AsF + buf*ASZ2);
        const unsigned* Bs = (const unsigned*)(BsF + buf*BSZ);
#pragma unroll
        for (int ks = 0; ks < 4; ks++) {
            int kk = ks*8;
            unsigned a[4][4];
#pragma unroll
            for (int mi = 0; mi < 4; mi++) {
                int row = wm*64 + mi*16 + g;
                a[mi][0] = As[row*36 + kk + t];
                a[mi][1] = As[(row + 8)*36 + kk + t];
                a[mi][2] = As[row*36 + kk + t + 4];
                a[mi][3] = As[(row + 8)*36 + kk + t + 4];
            }
            unsigned b[8][2];
#pragma unroll
            for (int ni = 0; ni < 8; ni++) {
                int col = wn*64 + ni*8 + g;
                b[ni][0] = Bs[(kk + t)*136 + col];
                b[ni][1] = Bs[(kk + t + 4)*136 + col];
            }
#pragma unroll
            for (int mi = 0; mi < 4; mi++)
#pragma unroll
                for (int ni = 0; ni < 8; ni++)
                    mma_tf32(acc[mi][ni], a[mi], b[ni]);
        }
    };

    loadP(0, 0);
    cp_commit();
    if (NP > 1) loadP(32, 1);
    cp_commit();

    for (int p = 0; p < NP; p++) {
        cp_wait1();
        __syncthreads();
        int pn = p + 2;
        if (pn < NP) loadP(pn*32, pn % 3);
        cp_commit();
        compute(p % 3);
    }

    // ---- epilogue ----
#pragma unroll
    for (int mi = 0; mi < 4; mi++) {
        int r0 = m0 + wm*64 + mi*16 + g;
#pragma unroll
        for (int ni = 0; ni < 8; ni++) {
            int c0 = n0 + wn*64 + ni*8 + 2*t;
            float b0 = bias ? bias[c0] : 0.f;
            float b1 = bias ? bias[c0 + 1] : 0.f;
            float v0 = acc[mi][ni][0] + b0;
            float v1 = acc[mi][ni][1] + b1;
            float v2 = acc[mi][ni][2] + b0;
            float v3 = acc[mi][ni][3] + b1;
            if (resid) {
                v0 += resid[(long)r0*N + c0];
                v1 += resid[(long)r0*N + c0 + 1];
                v2 += resid[(long)(r0 + 8)*N + c0];
                v3 += resid[(long)(r0 + 8)*N + c0 + 1];
            }
            if (relu) {
                v0 = fmaxf(v0, 0.f); v1 = fmaxf(v1, 0.f);
                v2 = fmaxf(v2, 0.f); v3 = fmaxf(v3, 0.f);
            }
            if (rnd) {
                v0 = roundtf(v0); v1 = roundtf(v1);
                v2 = roundtf(v2); v3 = roundtf(v3);
            }
            C[(long)r0*N + c0]           = v0;
            C[(long)r0*N + c0 + 1]       = v1;
            C[(long)(r0 + 8)*N + c0]     = v2;
            C[(long)(r0 + 8)*N + c0 + 1] = v3;
        }
    }
}

// ============ tf32 GEMM NT, 128x128, cp.async 3-stage: C = A·Bt^T + bias ============
__global__ void __launch_bounds__(256)
k_gemm_nt_tc(const float* __restrict__ A, const float* __restrict__ Bt,
             const float* __restrict__ bias, float* __restrict__ C,
             int M, int N, int K) {
    extern __shared__ float smem[];
    float* AsF = smem;                   // [3][128][36]
    float* BsF = smem + 3*ASZ1;          // [3][128][36]  n-major

    const int tid = threadIdx.x;
    const int m0 = blockIdx.y * 128;
    const int n0 = blockIdx.x * 128;
    const int lane = tid & 31, wid = tid >> 5;
    const int wm = wid & 3, wn = wid >> 2;
    const int g = lane >> 2, t = lane & 3;

    float acc[2][8][4];
#pragma unroll
    for (int mi = 0; mi < 2; mi++)
#pragma unroll
        for (int ni = 0; ni < 8; ni++)
#pragma unroll
            for (int j = 0; j < 4; j++) acc[mi][ni][j] = 0.f;

    const int ar = tid >> 3;
    const int ac4 = (tid & 7) * 4;
    const int NP = K / 32;

    auto loadP = [&](int k0, int buf) {
        float* As = AsF + buf*ASZ1;
        float* Bs = BsF + buf*BSZ_NT;
#pragma unroll
        for (int i = 0; i < 4; i++)
            cp16(&As[(ar + i*32)*36 + ac4],
                 &A[(long)(m0 + ar + i*32)*K + k0 + ac4], 16);
#pragma unroll
        for (int i = 0; i < 4; i++)
            cp16(&Bs[(ar + i*32)*36 + ac4],
                 &Bt[(long)(n0 + ar + i*32)*K + k0 + ac4], 16);
    };

    auto compute = [&](int buf) {
        const unsigned* As = (const unsigned*)(AsF + buf*ASZ1);
        const unsigned* Bs = (const unsigned*)(BsF + buf*BSZ_NT);
#pragma unroll
        for (int ks = 0; ks < 4; ks++) {
            int kk = ks*8;
            unsigned a[2][4];
#pragma unroll
            for (int mi = 0; mi < 2; mi++) {
                int row = wm*32 + mi*16 + g;
                a[mi][0] = As[row*36 + kk + t];
                a[mi][1] = As[(row + 8)*36 + kk + t];
                a[mi][2] = As[row*36 + kk + t + 4];
                a[mi][3] = As[(row + 8)*36 + kk + t + 4];
            }
            unsigned b[8][2];
#pragma unroll
            for (int ni = 0; ni < 8; ni++) {
                int col = wn*64 + ni*8 + g;
                b[ni][0] = Bs[col*36 + kk + t];
                b[ni][1] = Bs[col*36 + kk + t + 4];
            }
#pragma unroll
            for (int mi = 0; mi < 2; mi++)
#pragma unroll
                for (int ni = 0; ni < 8; ni++)
                    mma_tf32(acc[mi][ni], a[mi], b[ni]);
        }
    };

    loadP(0, 0);
    cp_commit();
    if (NP > 1) loadP(32, 1);
    cp_commit();

    for (int p = 0; p < NP; p++) {
        cp_wait1();
        __syncthreads();
        int pn = p + 2;
        if (pn < NP) loadP(pn*32, pn % 3);
        cp_commit();
        compute(p % 3);
    }

#pragma unroll
    for (int mi = 0; mi < 2; mi++) {
        int r0 = m0 + wm*32 + mi*16 + g;
#pragma unroll
        for (int ni = 0; ni < 8; ni++) {
            int c0 = n0 + wn*64 + ni*8 + 2*t;
            float b0 = bias[c0], b1 = bias[c0 + 1];
            C[(long)r0*N + c0]           = acc[mi][ni][0] + b0;
            C[(long)r0*N + c0 + 1]       = acc[mi][ni][1] + b1;
            C[(long)(r0 + 8)*N + c0]     = acc[mi][ni][2] + b0;
            C[(long)(r0 + 8)*N + c0 + 1] = acc[mi][ni][3] + b1;
        }
    }
}

// ---------------- ACT step pieces ----------------
__global__ void k_active_chk() {
    __shared__ int any;
    if (threadIdx.x == 0) any = 0;
    __syncthreads();
    int loc = 0;
    for (int i = threadIdx.x; i < BL; i += blockDim.x)
        if (g_hp[i] < THRESHV && g_nu[i] < (float)NLMAX) loc = 1;
    if (loc) atomicOr(&any, 1);
    __syncthreads();
    if (threadIdx.x == 0) g_active = any;
}

// fused: build s, halting prob, LayerNorm1 -> xn (rounded)
__global__ void k_builds_ln(int t, const float* __restrict__ pw, const float* __restrict__ pb,
                            const float* __restrict__ lng, const float* __restrict__ lnb) {
    if (!g_active) return;
    int row = blockIdx.x;
    int l = row % LQ;
    int c0 = threadIdx.x, c1 = threadIdx.x + 256;
    float v0 = g_state[row*HD + c0] + g_tsig[l*HD + c0] + g_psig[t*HD + c0];
    float v1 = g_state[row*HD + c1] + g_tsig[l*HD + c1] + g_psig[t*HD + c1];
    g_s[row*HD + c0] = v0;
    g_s[row*HD + c1] = v1;
    float dot = v0*pw[c0] + v1*pw[c1];
    float tot = blockReduceSum(dot);
    if (threadIdx.x == 0)
        g_pr[row] = 1.f / (1.f + expf(-(tot + pb[0])));
    float mu = blockReduceSum(v0 + v1) / (float)HD;
    float d0 = v0 - mu, d1 = v1 - mu;
    float var = blockReduceSum(d0*d0 + d1*d1) / (float)(HD - 1);
    float inv = 1.f / (sqrtf(var) + EPSV);
    g_xn[row*HD + c0] = roundtf(lng[c0]*d0*inv + lnb[c0]);
    g_xn[row*HD + c1] = roundtf(lng[c1]*d1*inv + lnb[c1]);
}

__global__ void k_ln(const float* __restrict__ X, const float* __restrict__ g,
                     const float* __restrict__ b, float* __restrict__ Y) {
    if (!g_active) return;
    int row = blockIdx.x;
    const float* x = X + row*HD;
    float s = 0.f;
    for (int c = threadIdx.x; c < HD; c += blockDim.x) s += x[c];
    float mu = blockReduceSum(s) / (float)HD;
    float vs = 0.f;
    for (int c = threadIdx.x; c < HD; c += blockDim.x) {
        float d = x[c] - mu; vs += d*d;
    }
    float var = blockReduceSum(vs) / (float)(HD - 1);
    float inv = 1.f / (sqrtf(var) + EPSV);
    for (int c = threadIdx.x; c < HD; c += blockDim.x)
        Y[row*HD + c] = roundtf(g[c]*(x[c] - mu)*inv + b[c]);
}

// attention over fused qkv buffer: q at col h*64, k at 512+h*64, v at 1024+h*64
__global__ void k_attn() {
    if (!g_active) return;
    int bh = blockIdx.x;
    int b = bh / NHEAD, h = bh % NHEAD;
    __shared__ float ks[LQ*65];
    __shared__ float vs[LQ*65];
    __shared__ float qrow[4][DKH];
    __shared__ float ps[4][LQ + 1];
    int tid = threadIdx.x;
    long qbase = (long)(b*LQ)*QKVN + h*DKH;
    for (int i = tid; i < LQ*DKH; i += 128) {
        int j = i / DKH, d = i % DKH;
        ks[j*65 + d] = g_qkv[qbase + 512 + (long)j*QKVN + d];
        vs[j*65 + d] = g_qkv[qbase + 1024 + (long)j*QKVN + d];
    }
    __syncthreads();
    int w = tid >> 5, lane = tid & 31;
    for (int r = w; r < LQ; r += 4) {
        for (int d = lane; d < DKH; d += 32) qrow[w][d] = g_qkv[qbase + (long)r*QKVN + d];
        __syncwarp();
        float sc[3];
#pragma unroll
        for (int jj = 0; jj < 3; jj++) {
            int j = lane + jj*32;
            float a = -3.0e38f;
            if (j < LQ) {
                a = 0.f;
#pragma unroll
                for (int d = 0; d < DKH; d++) a += qrow[w][d]*ks[j*65 + d];
            }
            sc[jj] = a;
        }
        float mx = fmaxf(sc[0], fmaxf(sc[1], sc[2]));
#pragma unroll
        for (int o = 16; o; o >>= 1) mx = fmaxf(mx, __shfl_xor_sync(0xffffffffu, mx, o));
        float sum = 0.f;
#pragma unroll
        for (int jj = 0; jj < 3; jj++) {
            int j = lane + jj*32;
            float e = (j < LQ) ? expf(sc[jj] - mx) : 0.f;
            sc[jj] = e; sum += e;
        }
#pragma unroll
        for (int o = 16; o; o >>= 1) sum += __shfl_xor_sync(0xffffffffu, sum, o);
        float inv = 1.f / sum;
#pragma unroll
        for (int jj = 0; jj < 3; jj++) {
            int j = lane + jj*32;
            if (j < LQ) ps[w][j] = sc[jj]*inv;
        }
        __syncwarp();
        for (int d = lane; d < DKH; d += 32) {
            float a = 0.f;
#pragma unroll 8
            for (int j = 0; j < LQ; j++) a += ps[w][j]*vs[j*65 + d];
            g_ctx[(long)(b*LQ)*HD + h*DKH + (long)r*HD + d] = roundtf(a);
        }
        __syncwarp();
    }
}

__global__ void k_halt() {
    if (!g_active) return;
    int row = blockIdx.x;
    __shared__ float s_uw;
    if (threadIdx.x == 0) {
        float pr = g_pr[row], hp = g_hp[row], rem = g_rem[row], nu = g_nu[row];
        float still = (hp < 1.0f) ? 1.f : 0.f;
        float tot = hp + pr*still;
        float nh  = ((tot > THRESHV) ? 1.f : 0.f)*still;
        float st2 = ((tot <= THRESHV) ? 1.f : 0.f)*still;
        float hp2 = hp + pr*st2;
        float rem2 = rem + nh*(1.f - hp2);
        hp2 = hp2 + nh*rem2;
        float nu2 = nu + st2 + nh;
        float uw = pr*st2 + nh*rem2;
        g_hp[row] = hp2; g_rem[row] = rem2; g_nu[row] = nu2;
        s_uw = uw;
    }
    __syncthreads();
    float uw = s_uw;
    for (int c = threadIdx.x; c < HD; c += blockDim.x) {
        int i = row*HD + c;
        float y = g_y[i];
        g_prev[i]  = y*uw + g_prev[i]*(1.f - uw);
        g_state[i] = y;
    }
}

// ---------------- pooling / softmax / tail ----------------
__global__ void k_pool() {
    int b = blockIdx.x;
    for (int c = threadIdx.x; c < HD; c += blockDim.x) {
        float a = 0.f;
        for (int l = 0; l < LQ; l++) a += g_prev[(b*LQ + l)*HD + c];
        g_pooled[b*HD + c] = roundtf(a / (float)LQ);
    }
}

__global__ void k_softmax(float* __restrict__ out) {
    int b = blockIdx.x;
    const float* a = out + (long)b*VOC;
    float* sm = out + (long)BB*VOC + (long)b*VOC;
    float mx = -3.0e38f;
    for (int i = threadIdx.x; i < VOC; i += blockDim.x) mx = fmaxf(mx, a[i]);
    float M = blockReduceMax(mx);
    float s = 0.f;
    for (int i = threadIdx.x; i < VOC; i += blockDim.x) s += expf(a[i] - M);
    float S = blockReduceSum(s);
    float inv = 1.f / S;
    for (int i = threadIdx.x; i < VOC; i += blockDim.x) sm[i] = expf(a[i] - M)*inv;
}

__global__ void k_tail(float* __restrict__ out) {
    int i = blockIdx.x * blockDim.x + threadIdx.x;
    if (i < BL) {
        out[(long)2*BB*VOC + i]      = g_rem[i];
        out[(long)2*BB*VOC + BL + i] = g_nu[i];
    }
}

// ---------------- host ----------------
extern "C" void kernel_launch(void* const* d_in, const int* in_sizes, int n_in,
                              void* d_out, int out_size) {
    const int*   story = (const int*)d_in[0];
    const int*   query = (const int*)d_in[1];
    const float* emb   = (const float*)d_in[2];
    const float* mask  = (const float*)d_in[3];
    const float* projw = (const float*)d_in[4];
    const float* ln1g  = (const float*)d_in[5];
    const float* ln1b  = (const float*)d_in[6];
    const float* wq    = (const float*)d_in[7];
    const float* wk    = (const float*)d_in[8];
    const float* wv    = (const float*)d_in[9];
    const float* wo    = (const float*)d_in[10];
    const float* c1w   = (const float*)d_in[11];
    const float* c1b   = (const float*)d_in[12];
    const float* c2w   = (const float*)d_in[13];
    const float* c2b   = (const float*)d_in[14];
    const float* ln2g  = (const float*)d_in[15];
    const float* ln2b  = (const float*)d_in[16];
    const float* pw    = (const float*)d_in[17];
    const float* pb    = (const float*)d_in[18];
    const float* outb  = (const float*)d_in[19];
    float* out = (float*)d_out;

    void *p_x, *p_state, *p_s, *p_xn, *p_qkv, *p_ctx, *p_s2, *p_xn2,
         *p_y, *p_mid, *p_w1t, *p_w2t, *p_pooled, *p_wr, *p_wqkv, *p_embr;
    cudaGetSymbolAddress(&p_x, g_x);
    cudaGetSymbolAddress(&p_state, g_state);
    cudaGetSymbolAddress(&p_s, g_s);
    cudaGetSymbolAddress(&p_xn, g_xn);
    cudaGetSymbolAddress(&p_qkv, g_qkv);
    cudaGetSymbolAddress(&p_ctx, g_ctx);
    cudaGetSymbolAddress(&p_s2, g_s2);
    cudaGetSymbolAddress(&p_xn2, g_xn2);
    cudaGetSymbolAddress(&p_y, g_y);
    cudaGetSymbolAddress(&p_mid, g_mid);
    cudaGetSymbolAddress(&p_w1t, g_w1t);
    cudaGetSymbolAddress(&p_w2t, g_w2t);
    cudaGetSymbolAddress(&p_pooled, g_pooled);
    cudaGetSymbolAddress(&p_wr, g_wr);
    cudaGetSymbolAddress(&p_wqkv, g_wqkv);
    cudaGetSymbolAddress(&p_embr, g_embr);
    const float* wr = (const float*)p_wr;

    cudaFuncSetAttribute(k_gemm_tc, cudaFuncAttributeMaxDynamicSharedMemorySize, SMEM_NN);
    cudaFuncSetAttribute(k_gemm_nt_tc, cudaFuncAttributeMaxDynamicSharedMemorySize, SMEM_NT);

    k_sigs<<<(LQ*HD + NLMAX*HD + 255)/256, 256>>>();
    k_wt1<<<(3*HD*FSZ + 255)/256, 256>>>(c1w);
    k_wt2<<<(3*FSZ*HD + 255)/256, 256>>>(c2w);
    k_roundw<<<(HD*HD + 255)/256, 256>>>(projw, wo);
    k_wqkv<<<(HD*QKVN + 255)/256, 256>>>(wq, wk, wv);
    k_rounde<<<(VOC*HD + 255)/256, 256>>>(emb);
    k_init<<<(BL*HD + 255)/256, 256>>>();
    k_embed<<<BL, 128>>>(story, query, emb, mask);

    // state = x @ proj_w
    {
        dim3 grid(HD/128, BL/256);
        k_gemm_tc<<<grid, 256, SMEM_NN>>>((const float*)p_x, wr + 0*HD*HD, (float*)p_state,
                                          BL, HD, HD, nullptr, nullptr, 0, 0, 0, 0, 0, 0);
    }

    for (int t = 0; t < NLMAX; t++) {
        k_active_chk<<<1, 1024>>>();
        k_builds_ln<<<BL, 256>>>(t, pw, pb, ln1g, ln1b);
        // fused QKV
        {
            dim3 gq(QKVN/128, BL/256);
            k_gemm_tc<<<gq, 256, SMEM_NN>>>((const float*)p_xn, (const float*)p_wqkv,
                                            (float*)p_qkv, BL, QKVN, HD,
                                            nullptr, nullptr, 0, 1, 0, 0, 0, 0);
        }
        k_attn<<<BB*NHEAD, 128>>>();
        {
            dim3 go(HD/128, BL/256);
            k_gemm_tc<<<go, 256, SMEM_NN>>>((const float*)p_ctx, wr + 4*HD*HD, (float*)p_s2,
                                            BL, HD, HD, nullptr, (const float*)p_s,
                                            0, 1, 0, 0, 0, 0);
        }
        k_ln<<<BL, 256>>>((const float*)p_s2, ln2g, ln2b, (float*)p_xn2);
        {
            dim3 gc1(FSZ/128, BL/256);
            k_gemm_tc<<<gc1, 256, SMEM_NN>>>((const float*)p_xn2, (const float*)p_w1t, (float*)p_mid,
                                             BL, FSZ, 3*HD, c1b, nullptr, 1, 1, 1, HD, 9, 1);
            dim3 gc2(HD/128, BL/256);
            k_gemm_tc<<<gc2, 256, SMEM_NN>>>((const float*)p_mid, (const float*)p_w2t, (float*)p_y,
                                             BL, HD, 3*FSZ, c2b, (const float*)p_s2, 0, 1, 1, FSZ, 11, 0);
        }
        k_halt<<<BL, 256>>>();
    }

    k_pool<<<BB, 256>>>();
    {
        dim3 grid(VOC/128, BB/128);
        k_gemm_nt_tc<<<grid, 256, SMEM_NT>>>((const float*)p_pooled, (const float*)p_embr,
                                             outb, out, BB, VOC, HD);
    }
    k_softmax<<<BB, 1024>>>(out);
    k_tail<<<(BL + 255)/256, 256>>>(out);
}

// round 9
// speedup vs baseline: 1.4484x; 1.4484x over previous
#include <cuda_runtime.h>
#include <cuda_fp16.h>
#include <math.h>

#define BB     256
#define MEMN   70
#define SLENQ  11
#define LQ     71
#define BL     (BB*LQ)       // 18176
#define HD     512
#define FSZ    2048
#define NHEAD  8
#define DKH    64
#define NLMAX  6
#define VOC    32000
#define QKVN   1536
#define THRESHV 0.9f
#define EPSV   1e-6f

// fp16 GEMM smem: 3 stages x (A[128][40] + B[128][40]) halves
#define ASTRIDE 40
#define STG_H  (128*ASTRIDE)
#define SMEM_H (3*2*STG_H*2)   // 61440 bytes

// ---------------- scratch (device globals; no allocation) ----------------
__device__ float  g_state[BL*HD];
__device__ float  g_prev[BL*HD];
__device__ float  g_s[BL*HD];
__device__ float  g_s2[BL*HD];
__device__ float  g_y[BL*HD];
__device__ __half g_xh[BL*HD];
__device__ __half g_xnh[BL*HD];
__device__ __half g_xn2h[BL*HD];
__device__ __half g_qkvh[BL*QKVN];
__device__ __half g_ctxh[BL*HD];
__device__ __half g_midh[BL*FSZ];
__device__ __half g_pwt[HD*HD];          // [N][K] proj_w^T
__device__ __half g_wot[HD*HD];          // [N][K] wo^T
__device__ __half g_wqkvt[QKVN*HD];      // [1536][512], q-scale baked
__device__ __half g_w1t[FSZ*3*HD];       // [2048][1536]
__device__ __half g_w2t[HD*3*FSZ];       // [512][6144]
__device__ __half g_embh[VOC*HD];        // [32000][512]
__device__ __half g_pooledh[BB*HD];
__device__ float  g_tsig[LQ*HD];
__device__ float  g_psig[NLMAX*HD];
__device__ float  g_hp[BL], g_rem[BL], g_nu[BL], g_pr[BL];
__device__ int    g_active;

// ---------------- helpers ----------------
__device__ __forceinline__ void mma_f16(float* d, const unsigned* a, const unsigned* b) {
    asm volatile(
        "mma.sync.aligned.m16n8k16.row.col.f32.f16.f16.f32 "
        "{%0,%1,%2,%3}, {%4,%5,%6,%7}, {%8,%9}, {%0,%1,%2,%3};"
        : "+f"(d[0]), "+f"(d[1]), "+f"(d[2]), "+f"(d[3])
        : "r"(a[0]), "r"(a[1]), "r"(a[2]), "r"(a[3]), "r"(b[0]), "r"(b[1]));
}

__device__ __forceinline__ void cp16(void* dst, const void* src, int ss) {
    unsigned d = (unsigned)__cvta_generic_to_shared(dst);
    asm volatile("cp.async.cg.shared.global [%0], [%1], 16, %2;"
                 :: "r"(d), "l"(src), "r"(ss));
}
__device__ __forceinline__ void cp_commit() { asm volatile("cp.async.commit_group;"); }
__device__ __forceinline__ void cp_wait1()  { asm volatile("cp.async.wait_group 1;"); }

__device__ __forceinline__ float blockReduceSum(float v) {
    __shared__ float sh[32];
    __shared__ float res;
    int lane = threadIdx.x & 31, wid = threadIdx.x >> 5;
#pragma unroll
    for (int o = 16; o; o >>= 1) v += __shfl_xor_sync(0xffffffffu, v, o);
    if (lane == 0) sh[wid] = v;
    __syncthreads();
    if (wid == 0) {
        float x = (lane < (int)(blockDim.x >> 5)) ? sh[lane] : 0.f;
#pragma unroll
        for (int o = 16; o; o >>= 1) x += __shfl_xor_sync(0xffffffffu, x, o);
        if (lane == 0) res = x;
    }
    __syncthreads();
    return res;
}

__device__ __forceinline__ float blockReduceMax(float v) {
    __shared__ float sh[32];
    __shared__ float res;
    int lane = threadIdx.x & 31, wid = threadIdx.x >> 5;
#pragma unroll
    for (int o = 16; o; o >>= 1) v = fmaxf(v, __shfl_xor_sync(0xffffffffu, v, o));
    if (lane == 0) sh[wid] = v;
    __syncthreads();
    if (wid == 0) {
        float x = (lane < (int)(blockDim.x >> 5)) ? sh[lane] : -3.0e38f;
#pragma unroll
        for (int o = 16; o; o >>= 1) x = fmaxf(x, __shfl_xor_sync(0xffffffffu, x, o));
        if (lane == 0) res = x;
    }
    __syncthreads();
    return res;
}

// ---------------- init / signals / weight prep ----------------
__global__ void k_init() {
    int i = blockIdx.x * blockDim.x + threadIdx.x;
    if (i < BL*HD) g_prev[i] = 0.f;
    if (i < BL) { g_hp[i] = 0.f; g_rem[i] = 0.f; g_nu[i] = 0.f; }
}

__global__ void k_sigs() {
    int i = blockIdx.x * blockDim.x + threadIdx.x;
    const float log_inc = logf(1e4f) / 255.f;
    if (i < LQ*HD) {
        int pos = i / HD, c = i % HD;
        int j = (c < 256) ? c : c - 256;
        float val = (float)pos * expf(-log_inc * (float)j);
        g_tsig[i] = (c < 256) ? sinf(val) : cosf(val);
    } else {
        int k = i - LQ*HD;
        if (k < NLMAX*HD) {
            int pos = k / HD, c = k % HD;
            int j = (c < 256) ? c : c - 256;
            float val = (float)pos * expf(-log_inc * (float)j);
            g_psig[k] = (c < 256) ? sinf(val) : cosf(val);
        }
    }
}

// conv1 weights -> [2048][1536] half; K index k = kk*512 + c
__global__ void k_w1t(const float* __restrict__ w) {
    int i = blockIdx.x * blockDim.x + threadIdx.x;
    if (i < FSZ*3*HD) {
        int n = i / (3*HD), k = i % (3*HD);
        int kk = k / HD, c = k % HD;
        g_w1t[i] = __float2half_rn(w[(n*HD + c)*3 + kk]);
    }
}

// conv2 weights -> [512][6144] half; k = kk*2048 + c
__global__ void k_w2t(const float* __restrict__ w) {
    int i = blockIdx.x * blockDim.x + threadIdx.x;
    if (i < HD*3*FSZ) {
        int n = i / (3*FSZ), k = i % (3*FSZ);
        int kk = k / FSZ, c = k % FSZ;
        g_w2t[i] = __float2half_rn(w[(n*FSZ + c)*3 + kk]);
    }
}

__global__ void k_wsq(const float* __restrict__ projw, const float* __restrict__ wo) {
    int i = blockIdx.x * blockDim.x + threadIdx.x;
    if (i < HD*HD) {
        int n = i / HD, k = i % HD;
        g_pwt[i] = __float2half_rn(projw[k*HD + n]);
        g_wot[i] = __float2half_rn(wo[k*HD + n]);
    }
}

__global__ void k_wqkv(const float* __restrict__ wq, const float* __restrict__ wk,
                       const float* __restrict__ wv) {
    int i = blockIdx.x * blockDim.x + threadIdx.x;
    if (i < QKVN*HD) {
        int n = i / HD, k = i % HD;
        float v;
        if (n < 512)       v = 0.125f * wq[k*HD + n];
        else if (n < 1024) v = wk[k*HD + n - 512];
        else               v = wv[k*HD + n - 1024];
        g_wqkvt[i] = __float2half_rn(v);
    }
}

__global__ void k_embh(const float* __restrict__ emb) {
    long i = (long)blockIdx.x * blockDim.x + threadIdx.x;
    if (i < (long)VOC*HD) g_embh[i] = __float2half_rn(emb[i]);
}

// ---------------- embedding (half output: feeds proj GEMM) ----------------
__global__ void k_embed(const int* __restrict__ story, const int* __restrict__ query,
                        const float* __restrict__ emb, const float* __restrict__ mask) {
    int row = blockIdx.x;
    int b = row / LQ, m = row % LQ;
    for (int c = threadIdx.x; c < HD; c += blockDim.x) {
        float acc = 0.f;
        if (m < MEMN) {
#pragma unroll
            for (int s = 0; s < SLENQ; s++) {
                int tok = story[(b*MEMN + m)*SLENQ + s];
                acc += emb[(long)tok*HD + c] * mask[s*HD + c];
            }
        } else {
#pragma unroll
            for (int s = 0; s < SLENQ; s++) {
                int tok = query[b*SLENQ + s];
                acc += emb[(long)tok*HD + c] * mask[s*HD + c];
            }
        }
        g_xh[row*HD + c] = __float2half_rn(acc);
    }
}

// ============ fp16 tensor-core GEMM, 128x128, cp.async 3-stage ============
// W is [N][K] half. C = act(A@W^T + bias + resid).
// conv!=0: A gathered from X[B,L,Cin] with kernel-pos shift; K = 3*Cin.
// Output: Cf (float) if non-null else Ch (half).
__global__ void __launch_bounds__(256)
k_gemm_h(const __half* __restrict__ A, const __half* __restrict__ W,
         float* __restrict__ Cf, __half* __restrict__ Ch,
         int M, int N, int K,
         const float* __restrict__ bias, const float* __restrict__ resid,
         int relu, int chk, int conv, int Cin, int cshift) {
    if (chk && !g_active) return;
    extern __shared__ __half sm[];
    __half* AsB = sm;              // [3][128][40]
    __half* BsB = sm + 3*STG_H;    // [3][128][40]

    const int tid = threadIdx.x;
    const int m0 = blockIdx.y * 128;
    const int n0 = blockIdx.x * 128;
    const int lane = tid & 31, wid = tid >> 5;
    const int wm = wid & 3, wn = wid >> 2;   // warp tile 32x64
    const int g = lane >> 2, t = lane & 3;

    float acc[2][8][4];
#pragma unroll
    for (int mi = 0; mi < 2; mi++)
#pragma unroll
        for (int ni = 0; ni < 8; ni++)
#pragma unroll
            for (int j = 0; j < 4; j++) acc[mi][ni][j] = 0.f;

    const int NP = K / 32;

    auto loadP = [&](int k0, int buf) {
        __half* As = AsB + buf*STG_H;
        __half* Bs = BsB + buf*STG_H;
        if (conv) {
            int kk = k0 >> cshift;
            int cb = k0 & (Cin - 1);
#pragma unroll
            for (int i = 0; i < 2; i++) {
                int idx = tid + i*256;
                int row = idx >> 2, ch = (idx & 3)*8;
                int m = m0 + row;
                int b = m / LQ, l = m - b*LQ;
                int lp = l + kk - 1;
                int ok = (lp >= 0 && lp < LQ);
                const __half* src = &A[(long)(b*LQ + (ok ? lp : 0))*Cin + cb + ch];
                cp16(&As[row*ASTRIDE + ch], src, ok ? 16 : 0);
            }
        } else {
#pragma unroll
            for (int i = 0; i < 2; i++) {
                int idx = tid + i*256;
                int row = idx >> 2, ch = (idx & 3)*8;
                cp16(&As[row*ASTRIDE + ch], &A[(long)(m0 + row)*K + k0 + ch], 16);
            }
        }
#pragma unroll
        for (int i = 0; i < 2; i++) {
            int idx = tid + i*256;
            int row = idx >> 2, ch = (idx & 3)*8;
            cp16(&Bs[row*ASTRIDE + ch], &W[(long)(n0 + row)*K + k0 + ch], 16);
        }
    };

    auto compute = [&](int buf) {
        const __half* As = AsB + buf*STG_H;
        const __half* Bs = BsB + buf*STG_H;
#pragma unroll
        for (int ks = 0; ks < 2; ks++) {
            int kk = ks*16;
            unsigned a[2][4];
#pragma unroll
            for (int mi = 0; mi < 2; mi++) {
                int row = wm*32 + mi*16 + g;
                a[mi][0] = *(const unsigned*)&As[row*ASTRIDE + kk + 2*t];
                a[mi][1] = *(const unsigned*)&As[(row + 8)*ASTRIDE + kk + 2*t];
                a[mi][2] = *(const unsigned*)&As[row*ASTRIDE + kk + 2*t + 8];
                a[mi][3] = *(const unsigned*)&As[(row + 8)*ASTRIDE + kk + 2*t + 8];
            }
            unsigned b[8][2];
#pragma unroll
            for (int ni = 0; ni < 8; ni++) {
                int col = wn*64 + ni*8 + g;
                b[ni][0] = *(const unsigned*)&Bs[col*ASTRIDE + kk + 2*t];
                b[ni][1] = *(const unsigned*)&Bs[col*ASTRIDE + kk + 2*t + 8];
            }
#pragma unroll
            for (int mi = 0; mi < 2; mi++)
#pragma unroll
                for (int ni = 0; ni < 8; ni++)
                    mma_f16(acc[mi][ni], a[mi], b[ni]);
        }
    };

    loadP(0, 0);
    cp_commit();
    if (NP > 1) loadP(32, 1);
    cp_commit();

    for (int p = 0; p < NP; p++) {
        cp_wait1();
        __syncthreads();
        int pn = p + 2;
        if (pn < NP) loadP(pn*32, pn % 3);
        cp_commit();
        compute(p % 3);
    }

    // ---- epilogue ----
#pragma unroll
    for (int mi = 0; mi < 2; mi++) {
        int r0 = m0 + wm*32 + mi*16 + g;
#pragma unroll
        for (int ni = 0; ni < 8; ni++) {
            int c0 = n0 + wn*64 + ni*8 + 2*t;
            float b0 = bias ? bias[c0] : 0.f;
            float b1 = bias ? bias[c0 + 1] : 0.f;
            float v0 = acc[mi][ni][0] + b0;
            float v1 = acc[mi][ni][1] + b1;
            float v2 = acc[mi][ni][2] + b0;
            float v3 = acc[mi][ni][3] + b1;
            if (resid) {
                v0 += resid[(long)r0*N + c0];
                v1 += resid[(long)r0*N + c0 + 1];
                v2 += resid[(long)(r0 + 8)*N + c0];
                v3 += resid[(long)(r0 + 8)*N + c0 + 1];
            }
            if (relu) {
                v0 = fmaxf(v0, 0.f); v1 = fmaxf(v1, 0.f);
                v2 = fmaxf(v2, 0.f); v3 = fmaxf(v3, 0.f);
            }
            if (Cf) {
                Cf[(long)r0*N + c0]           = v0;
                Cf[(long)r0*N + c0 + 1]       = v1;
                Cf[(long)(r0 + 8)*N + c0]     = v2;
                Cf[(long)(r0 + 8)*N + c0 + 1] = v3;
            } else {
                __half2 h01 = __floats2half2_rn(v0, v1);
                __half2 h23 = __floats2half2_rn(v2, v3);
                *(__half2*)&Ch[(long)r0*N + c0]       = h01;
                *(__half2*)&Ch[(long)(r0 + 8)*N + c0] = h23;
            }
        }
    }
}

// ---------------- ACT step pieces ----------------
__global__ void k_active_chk() {
    __shared__ int any;
    if (threadIdx.x == 0) any = 0;
    __syncthreads();
    int loc = 0;
    for (int i = threadIdx.x; i < BL; i += blockDim.x)
        if (g_hp[i] < THRESHV && g_nu[i] < (float)NLMAX) loc = 1;
    if (loc) atomicOr(&any, 1);
    __syncthreads();
    if (threadIdx.x == 0) g_active = any;
}

// fused: build s (fp32), halting prob, LayerNorm1 -> xn (half)
__global__ void k_builds_ln(int t, const float* __restrict__ pw, const float* __restrict__ pb,
                            const float* __restrict__ lng, const float* __restrict__ lnb) {
    if (!g_active) return;
    int row = blockIdx.x;
    int l = row % LQ;
    int c0 = threadIdx.x, c1 = threadIdx.x + 256;
    float v0 = g_state[row*HD + c0] + g_tsig[l*HD + c0] + g_psig[t*HD + c0];
    float v1 = g_state[row*HD + c1] + g_tsig[l*HD + c1] + g_psig[t*HD + c1];
    g_s[row*HD + c0] = v0;
    g_s[row*HD + c1] = v1;
    float dot = v0*pw[c0] + v1*pw[c1];
    float tot = blockReduceSum(dot);
    if (threadIdx.x == 0)
        g_pr[row] = 1.f / (1.f + expf(-(tot + pb[0])));
    float mu = blockReduceSum(v0 + v1) / (float)HD;
    float d0 = v0 - mu, d1 = v1 - mu;
    float var = blockReduceSum(d0*d0 + d1*d1) / (float)(HD - 1);
    float inv = 1.f / (sqrtf(var) + EPSV);
    g_xnh[row*HD + c0] = __float2half_rn(lng[c0]*d0*inv + lnb[c0]);
    g_xnh[row*HD + c1] = __float2half_rn(lng[c1]*d1*inv + lnb[c1]);
}

// LayerNorm2: fp32 in (s2), half out (xn2h)
__global__ void k_ln(const float* __restrict__ X, const float* __restrict__ g,
                     const float* __restrict__ b, __half* __restrict__ Y) {
    if (!g_active) return;
    int row = blockIdx.x;
    const float* x = X + row*HD;
    int c0 = threadIdx.x, c1 = threadIdx.x + 256;
    float x0 = x[c0], x1 = x[c1];
    float mu = blockReduceSum(x0 + x1) / (float)HD;
    float d0 = x0 - mu, d1 = x1 - mu;
    float var = blockReduceSum(d0*d0 + d1*d1) / (float)(HD - 1);
    float inv = 1.f / (sqrtf(var) + EPSV);
    Y[row*HD + c0] = __float2half_rn(g[c0]*d0*inv + b[c0]);
    Y[row*HD + c1] = __float2half_rn(g[c1]*d1*inv + b[c1]);
}

// attention over fused half qkv: q at col h*64, k at 512+h*64, v at 1024+h*64
__global__ void k_attn() {
    if (!g_active) return;
    int bh = blockIdx.x;
    int b = bh / NHEAD, h = bh % NHEAD;
    __shared__ float ks[LQ*65];
    __shared__ float vs[LQ*65];
    __shared__ float qrow[4][DKH];
    __shared__ float ps[4][LQ + 1];
    int tid = threadIdx.x;
    long qbase = (long)(b*LQ)*QKVN + h*DKH;
    for (int i = tid; i < LQ*DKH; i += 128) {
        int j = i / DKH, d = i % DKH;
        ks[j*65 + d] = __half2float(g_qkvh[qbase + 512 + (long)j*QKVN + d]);
        vs[j*65 + d] = __half2float(g_qkvh[qbase + 1024 + (long)j*QKVN + d]);
    }
    __syncthreads();
    int w = tid >> 5, lane = tid & 31;
    for (int r = w; r < LQ; r += 4) {
        for (int d = lane; d < DKH; d += 32)
            qrow[w][d] = __half2float(g_qkvh[qbase + (long)r*QKVN + d]);
        __syncwarp();
        float sc[3];
#pragma unroll
        for (int jj = 0; jj < 3; jj++) {
            int j = lane + jj*32;
            float a = -3.0e38f;
            if (j < LQ) {
                a = 0.f;
#pragma unroll
                for (int d = 0; d < DKH; d++) a += qrow[w][d]*ks[j*65 + d];
            }
            sc[jj] = a;
        }
        float mx = fmaxf(sc[0], fmaxf(sc[1], sc[2]));
#pragma unroll
        for (int o = 16; o; o >>= 1) mx = fmaxf(mx, __shfl_xor_sync(0xffffffffu, mx, o));
        float sum = 0.f;
#pragma unroll
        for (int jj = 0; jj < 3; jj++) {
            int j = lane + jj*32;
            float e = (j < LQ) ? expf(sc[jj] - mx) : 0.f;
            sc[jj] = e; sum += e;
        }
#pragma unroll
        for (int o = 16; o; o >>= 1) sum += __shfl_xor_sync(0xffffffffu, sum, o);
        float inv = 1.f / sum;
#pragma unroll
        for (int jj = 0; jj < 3; jj++) {
            int j = lane + jj*32;
            if (j < LQ) ps[w][j] = sc[jj]*inv;
        }
        __syncwarp();
        for (int d = lane; d < DKH; d += 32) {
            float a = 0.f;
#pragma unroll 8
            for (int j = 0; j < LQ; j++) a += ps[w][j]*vs[j*65 + d];
            g_ctxh[(long)(b*LQ)*HD + h*DKH + (long)r*HD + d] = __float2half_rn(a);
        }
        __syncwarp();
    }
}

__global__ void k_halt() {
    if (!g_active) return;
    int row = blockIdx.x;
    __shared__ float s_uw;
    if (threadIdx.x == 0) {
        float pr = g_pr[row], hp = g_hp[row], rem = g_rem[row], nu = g_nu[row];
        float still = (hp < 1.0f) ? 1.f : 0.f;
        float tot = hp + pr*still;
        float nh  = ((tot > THRESHV) ? 1.f : 0.f)*still;
        float st2 = ((tot <= THRESHV) ? 1.f : 0.f)*still;
        float hp2 = hp + pr*st2;
        float rem2 = rem + nh*(1.f - hp2);
        hp2 = hp2 + nh*rem2;
        float nu2 = nu + st2 + nh;
        float uw = pr*st2 + nh*rem2;
        g_hp[row] = hp2; g_rem[row] = rem2; g_nu[row] = nu2;
        s_uw = uw;
    }
    __syncthreads();
    float uw = s_uw;
    for (int c = threadIdx.x; c < HD; c += blockDim.x) {
        int i = row*HD + c;
        float y = g_y[i];
        g_prev[i]  = y*uw + g_prev[i]*(1.f - uw);
        g_state[i] = y;
    }
}

// ---------------- pooling / softmax / tail ----------------
__global__ void k_pool() {
    int b = blockIdx.x;
    for (int c = threadIdx.x; c < HD; c += blockDim.x) {
        float a = 0.f;
        for (int l = 0; l < LQ; l++) a += g_prev[(b*LQ + l)*HD + c];
        g_pooledh[b*HD + c] = __float2half_rn(a / (float)LQ);
    }
}

__global__ void k_softmax(float* __restrict__ out) {
    int b = blockIdx.x;
    const float* a = out + (long)b*VOC;
    float* sm = out + (long)BB*VOC + (long)b*VOC;
    float mx = -3.0e38f;
    for (int i = threadIdx.x; i < VOC; i += blockDim.x) mx = fmaxf(mx, a[i]);
    float M = blockReduceMax(mx);
    float s = 0.f;
    for (int i = threadIdx.x; i < VOC; i += blockDim.x) s += expf(a[i] - M);
    float S = blockReduceSum(s);
    float inv = 1.f / S;
    for (int i = threadIdx.x; i < VOC; i += blockDim.x) sm[i] = expf(a[i] - M)*inv;
}

__global__ void k_tail(float* __restrict__ out) {
    int i = blockIdx.x * blockDim.x + threadIdx.x;
    if (i < BL) {
        out[(long)2*BB*VOC + i]      = g_rem[i];
        out[(long)2*BB*VOC + BL + i] = g_nu[i];
    }
}

// ---------------- host ----------------
extern "C" void kernel_launch(void* const* d_in, const int* in_sizes, int n_in,
                              void* d_out, int out_size) {
    const int*   story = (const int*)d_in[0];
    const int*   query = (const int*)d_in[1];
    const float* emb   = (const float*)d_in[2];
    const float* mask  = (const float*)d_in[3];
    const float* projw = (const float*)d_in[4];
    const float* ln1g  = (const float*)d_in[5];
    const float* ln1b  = (const float*)d_in[6];
    const float* wq    = (const float*)d_in[7];
    const float* wk    = (const float*)d_in[8];
    const float* wv    = (const float*)d_in[9];
    const float* wo    = (const float*)d_in[10];
    const float* c1w   = (const float*)d_in[11];
    const float* c1b   = (const float*)d_in[12];
    const float* c2w   = (const float*)d_in[13];
    const float* c2b   = (const float*)d_in[14];
    const float* ln2g  = (const float*)d_in[15];
    const float* ln2b  = (const float*)d_in[16];
    const float* pw    = (const float*)d_in[17];
    const float* pb    = (const float*)d_in[18];
    const float* outb  = (const float*)d_in[19];
    float* out = (float*)d_out;

    void *p_state, *p_s, *p_s2, *p_y, *p_xh, *p_xnh, *p_xn2h, *p_qkvh, *p_ctxh,
         *p_midh, *p_pwt, *p_wot, *p_wqkvt, *p_w1t, *p_w2t, *p_embh, *p_pooledh;
    cudaGetSymbolAddress(&p_state, g_state);
    cudaGetSymbolAddress(&p_s, g_s);
    cudaGetSymbolAddress(&p_s2, g_s2);
    cudaGetSymbolAddress(&p_y, g_y);
    cudaGetSymbolAddress(&p_xh, g_xh);
    cudaGetSymbolAddress(&p_xnh, g_xnh);
    cudaGetSymbolAddress(&p_xn2h, g_xn2h);
    cudaGetSymbolAddress(&p_qkvh, g_qkvh);
    cudaGetSymbolAddress(&p_ctxh, g_ctxh);
    cudaGetSymbolAddress(&p_midh, g_midh);
    cudaGetSymbolAddress(&p_pwt, g_pwt);
    cudaGetSymbolAddress(&p_wot, g_wot);
    cudaGetSymbolAddress(&p_wqkvt, g_wqkvt);
    cudaGetSymbolAddress(&p_w1t, g_w1t);
    cudaGetSymbolAddress(&p_w2t, g_w2t);
    cudaGetSymbolAddress(&p_embh, g_embh);
    cudaGetSymbolAddress(&p_pooledh, g_pooledh);

    cudaFuncSetAttribute(k_gemm_h, cudaFuncAttributeMaxDynamicSharedMemorySize, SMEM_H);

    k_sigs<<<(LQ*HD + NLMAX*HD + 255)/256, 256>>>();
    k_w1t<<<(FSZ*3*HD + 255)/256, 256>>>(c1w);
    k_w2t<<<(HD*3*FSZ + 255)/256, 256>>>(c2w);
    k_wsq<<<(HD*HD + 255)/256, 256>>>(projw, wo);
    k_wqkv<<<(QKVN*HD + 255)/256, 256>>>(wq, wk, wv);
    k_embh<<<(VOC*HD + 255)/256, 256>>>(emb);
    k_init<<<(BL*HD + 255)/256, 256>>>();
    k_embed<<<BL, 128>>>(story, query, emb, mask);

    // state = x @ proj_w  (fp32 out)
    {
        dim3 grid(HD/128, BL/128);
        k_gemm_h<<<grid, 256, SMEM_H>>>((const __half*)p_xh, (const __half*)p_pwt,
                                        (float*)p_state, nullptr, BL, HD, HD,
                                        nullptr, nullptr, 0, 0, 0, 0, 0);
    }

    for (int t = 0; t < NLMAX; t++) {
        k_active_chk<<<1, 1024>>>();
        k_builds_ln<<<BL, 256>>>(t, pw, pb, ln1g, ln1b);
        // fused QKV (half out)
        {
            dim3 gq(QKVN/128, BL/128);
            k_gemm_h<<<gq, 256, SMEM_H>>>((const __half*)p_xnh, (const __half*)p_wqkvt,
                                          nullptr, (__half*)p_qkvh, BL, QKVN, HD,
                                          nullptr, nullptr, 0, 1, 0, 0, 0);
        }
        k_attn<<<BB*NHEAD, 128>>>();
        // O-proj + residual s (fp32 out)
        {
            dim3 go(HD/128, BL/128);
            k_gemm_h<<<go, 256, SMEM_H>>>((const __half*)p_ctxh, (const __half*)p_wot,
                                          (float*)p_s2, nullptr, BL, HD, HD,
                                          nullptr, (const float*)p_s, 0, 1, 0, 0, 0);
        }
        k_ln<<<BL, 256>>>((const float*)p_s2, ln2g, ln2b, (__half*)p_xn2h);
        // conv1: relu, half out
        {
            dim3 gc1(FSZ/128, BL/128);
            k_gemm_h<<<gc1, 256, SMEM_H>>>((const __half*)p_xn2h, (const __half*)p_w1t,
                                           nullptr, (__half*)p_midh, BL, FSZ, 3*HD,
                                           c1b, nullptr, 1, 1, 1, HD, 9);
        }
        // conv2 + residual s2 (fp32 out)
        {
            dim3 gc2(HD/128, BL/128);
            k_gemm_h<<<gc2, 256, SMEM_H>>>((const __half*)p_midh, (const __half*)p_w2t,
                                           (float*)p_y, nullptr, BL, HD, 3*FSZ,
                                           c2b, (const float*)p_s2, 0, 1, 1, FSZ, 11);
        }
        k_halt<<<BL, 256>>>();
    }

    k_pool<<<BB, 256>>>();
    // a_hat = pooled @ emb^T + out_b  (emb already [N][K])
    {
        dim3 grid(VOC/128, BB/128);
        k_gemm_h<<<grid, 256, SMEM_H>>>((const __half*)p_pooledh, (const __half*)p_embh,
                                        out, nullptr, BB, VOC, HD,
                                        outb, nullptr, 0, 0, 0, 0, 0);
    }
    k_softmax<<<BB, 1024>>>(out);
    k_tail<<<(BL + 255)/256, 256>>>(out);
}

// round 12
// speedup vs baseline: 1.6776x; 1.1582x over previous
#include <cuda_runtime.h>
#include <cuda_fp16.h>
#include <math.h>
#include <cstdint>

#define BB     256
#define MEMN   70
#define SLENQ  11
#define LQ     71
#define BL     (BB*LQ)       // 18176
#define HD     512
#define FSZ    2048
#define NHEAD  8
#define DKH    64
#define NLMAX  6
#define VOC    32000
#define QKVN   1536
#define THRESHV 0.9f
#define EPSV   1e-6f

// fp16 GEMM: 128x128 block, K-panel 64 halves, 3 stages, ldmatrix fragments
#define ASTRIDE 72
#define STG_HALVES (128*ASTRIDE)
#define STG_BYTES  (STG_HALVES*2)          // 18432
#define SMEM_H (3*2*STG_BYTES)             // 110592

// ---------------- scratch (device globals; no allocation) ----------------
__device__ float  g_state[BL*HD];
__device__ float  g_prev[BL*HD];
__device__ float  g_s[BL*HD];
__device__ float  g_s2[BL*HD];
__device__ float  g_y[BL*HD];
__device__ __half g_xh[BL*HD];
__device__ __half g_xnh[BL*HD];
__device__ __half g_xn2h[BL*HD];
__device__ __half g_qkvh[BL*QKVN];
__device__ __half g_ctxh[BL*HD];
__device__ __half g_midh[BL*FSZ];
__device__ __half g_pwt[HD*HD];          // [N][K] proj_w^T
__device__ __half g_wot[HD*HD];          // [N][K] wo^T
__device__ __half g_wqkvt[QKVN*HD];      // [1536][512], q-scale baked
__device__ __half g_w1t[FSZ*3*HD];       // [2048][1536]
__device__ __half g_w2t[HD*3*FSZ];       // [512][6144]
__device__ __half g_embh[VOC*HD];        // [32000][512]
__device__ __half g_pooledh[BB*HD];
__device__ float  g_tsig[LQ*HD];
__device__ float  g_psig[NLMAX*HD];
__device__ float  g_hp[BL], g_rem[BL], g_nu[BL], g_pr[BL];
__device__ int    g_active;

// ---------------- helpers ----------------
__device__ __forceinline__ uint32_t smem_u32(const void* p) {
    uint32_t a;
    asm("{ .reg .u64 t; cvta.to.shared.u64 t, %1; cvt.u32.u64 %0, t; }" : "=r"(a) : "l"(p));
    return a;
}

__device__ __forceinline__ void mma_f16(float* d, const unsigned* a, const unsigned* b) {
    asm volatile(
        "mma.sync.aligned.m16n8k16.row.col.f32.f16.f16.f32 "
        "{%0,%1,%2,%3}, {%4,%5,%6,%7}, {%8,%9}, {%0,%1,%2,%3};"
        : "+f"(d[0]), "+f"(d[1]), "+f"(d[2]), "+f"(d[3])
        : "r"(a[0]), "r"(a[1]), "r"(a[2]), "r"(a[3]), "r"(b[0]), "r"(b[1]));
}

__device__ __forceinline__ void ldsm4(unsigned& r0, unsigned& r1, unsigned& r2, unsigned& r3,
                                      uint32_t addr) {
    asm volatile("ldmatrix.sync.aligned.m8n8.x4.shared.b16 {%0,%1,%2,%3}, [%4];"
                 : "=r"(r0), "=r"(r1), "=r"(r2), "=r"(r3) : "r"(addr));
}

__device__ __forceinline__ void cp16s(uint32_t daddr, const void* src, int ss) {
    asm volatile("cp.async.cg.shared.global [%0], [%1], 16, %2;"
                 :: "r"(daddr), "l"(src), "r"(ss));
}
__device__ __forceinline__ void cp_commit() { asm volatile("cp.async.commit_group;"); }
__device__ __forceinline__ void cp_wait1()  { asm volatile("cp.async.wait_group 1;"); }

__device__ __forceinline__ float blockReduceSum(float v) {
    __shared__ float sh[32];
    __shared__ float res;
    int lane = threadIdx.x & 31, wid = threadIdx.x >> 5;
#pragma unroll
    for (int o = 16; o; o >>= 1) v += __shfl_xor_sync(0xffffffffu, v, o);
    if (lane == 0) sh[wid] = v;
    __syncthreads();
    if (wid == 0) {
        float x = (lane < (int)(blockDim.x >> 5)) ? sh[lane] : 0.f;
#pragma unroll
        for (int o = 16; o; o >>= 1) x += __shfl_xor_sync(0xffffffffu, x, o);
        if (lane == 0) res = x;
    }
    __syncthreads();
    return res;
}

__device__ __forceinline__ float blockReduceMax(float v) {
    __shared__ float sh[32];
    __shared__ float res;
    int lane = threadIdx.x & 31, wid = threadIdx.x >> 5;
#pragma unroll
    for (int o = 16; o; o >>= 1) v = fmaxf(v, __shfl_xor_sync(0xffffffffu, v, o));
    if (lane == 0) sh[wid] = v;
    __syncthreads();
    if (wid == 0) {
        float x = (lane < (int)(blockDim.x >> 5)) ? sh[lane] : -3.0e38f;
#pragma unroll
        for (int o = 16; o; o >>= 1) x = fmaxf(x, __shfl_xor_sync(0xffffffffu, x, o));
        if (lane == 0) res = x;
    }
    __syncthreads();
    return res;
}

// ---------------- init / signals / weight prep ----------------
__global__ void k_init() {
    int i = blockIdx.x * blockDim.x + threadIdx.x;
    if (i < BL*HD) g_prev[i] = 0.f;
    if (i < BL) { g_hp[i] = 0.f; g_rem[i] = 0.f; g_nu[i] = 0.f; }
}

__global__ void k_sigs() {
    int i = blockIdx.x * blockDim.x + threadIdx.x;
    const float log_inc = logf(1e4f) / 255.f;
    if (i < LQ*HD) {
        int pos = i / HD, c = i % HD;
        int j = (c < 256) ? c : c - 256;
        float val = (float)pos * expf(-log_inc * (float)j);
        g_tsig[i] = (c < 256) ? sinf(val) : cosf(val);
    } else {
        int k = i - LQ*HD;
        if (k < NLMAX*HD) {
            int pos = k / HD, c = k % HD;
            int j = (c < 256) ? c : c - 256;
            float val = (float)pos * expf(-log_inc * (float)j);
            g_psig[k] = (c < 256) ? sinf(val) : cosf(val);
        }
    }
}

__global__ void k_w1t(const float* __restrict__ w) {
    int i = blockIdx.x * blockDim.x + threadIdx.x;
    if (i < FSZ*3*HD) {
        int n = i / (3*HD), k = i % (3*HD);
        int kk = k / HD, c = k % HD;
        g_w1t[i] = __float2half_rn(w[(n*HD + c)*3 + kk]);
    }
}

__global__ void k_w2t(const float* __restrict__ w) {
    int i = blockIdx.x * blockDim.x + threadIdx.x;
    if (i < HD*3*FSZ) {
        int n = i / (3*FSZ), k = i % (3*FSZ);
        int kk = k / FSZ, c = k % FSZ;
        g_w2t[i] = __float2half_rn(w[(n*FSZ + c)*3 + kk]);
    }
}

__global__ void k_wsq(const float* __restrict__ projw, const float* __restrict__ wo) {
    int i = blockIdx.x * blockDim.x + threadIdx.x;
    if (i < HD*HD) {
        int n = i / HD, k = i % HD;
        g_pwt[i] = __float2half_rn(projw[k*HD + n]);
        g_wot[i] = __float2half_rn(wo[k*HD + n]);
    }
}

__global__ void k_wqkv(const float* __restrict__ wq, const float* __restrict__ wk,
                       const float* __restrict__ wv) {
    int i = blockIdx.x * blockDim.x + threadIdx.x;
    if (i < QKVN*HD) {
        int n = i / HD, k = i % HD;
        float v;
        if (n < 512)       v = 0.125f * wq[k*HD + n];
        else if (n < 1024) v = wk[k*HD + n - 512];
        else               v = wv[k*HD + n - 1024];
        g_wqkvt[i] = __float2half_rn(v);
    }
}

__global__ void k_embh(const float* __restrict__ emb) {
    long i = (long)blockIdx.x * blockDim.x + threadIdx.x;
    if (i < (long)VOC*HD) g_embh[i] = __float2half_rn(emb[i]);
}

__global__ void k_embed(const int* __restrict__ story, const int* __restrict__ query,
                        const float* __restrict__ emb, const float* __restrict__ mask) {
    int row = blockIdx.x;
    int b = row / LQ, m = row % LQ;
    for (int c = threadIdx.x; c < HD; c += blockDim.x) {
        float acc = 0.f;
        if (m < MEMN) {
#pragma unroll
            for (int s = 0; s < SLENQ; s++) {
                int tok = story[(b*MEMN + m)*SLENQ + s];
                acc += emb[(long)tok*HD + c] * mask[s*HD + c];
            }
        } else {
#pragma unroll
            for (int s = 0; s < SLENQ; s++) {
                int tok = query[b*SLENQ + s];
                acc += emb[(long)tok*HD + c] * mask[s*HD + c];
            }
        }
        g_xh[row*HD + c] = __float2half_rn(acc);
    }
}

// ============ fp16 GEMM: 128x128, K-panel 64, 3-stage cp.async, ldmatrix ============
// W is [N][K] half. C = act(A@W^T + bias + resid). conv: im2col gather on A.
__global__ void __launch_bounds__(256)
k_gemm_h(const __half* __restrict__ A, const __half* __restrict__ W,
         float* __restrict__ Cf, __half* __restrict__ Ch,
         int M, int N, int K,
         const float* __restrict__ bias, const float* __restrict__ resid,
         int relu, int chk, int conv, int Cin, int cshift) {
    if (chk && !g_active) return;
    extern __shared__ __half sm[];
    const uint32_t As0 = smem_u32(sm);                 // 3 stages A
    const uint32_t Bs0 = As0 + 3*STG_BYTES;            // 3 stages B

    const int tid = threadIdx.x;
    const int m0 = blockIdx.y * 128;
    const int n0 = blockIdx.x * 128;
    const int lane = tid & 31, wid = tid >> 5;
    const int wm = wid & 3, wn = wid >> 2;   // warp tile 32x64
    const int g = lane >> 2, t = lane & 3;
    const int sect = lane >> 3, lr = lane & 7;

    float acc[2][8][4];
#pragma unroll
    for (int mi = 0; mi < 2; mi++)
#pragma unroll
        for (int ni = 0; ni < 8; ni++)
#pragma unroll
            for (int j = 0; j < 4; j++) acc[mi][ni][j] = 0.f;

    // ldmatrix per-lane offsets (halves)
    uint32_t a_off[2], b_off[4];
#pragma unroll
    for (int mi = 0; mi < 2; mi++)
        a_off[mi] = (uint32_t)((wm*32 + mi*16 + (sect & 1)*8 + lr)*ASTRIDE + (sect >> 1)*8);
#pragma unroll
    for (int p = 0; p < 4; p++)
        b_off[p] = (uint32_t)((wn*64 + p*16 + (sect >> 1)*8 + lr)*ASTRIDE + (sect & 1)*8);

    const int NP = K >> 6;   // 64-half panels

    auto loadP = [&](int k0, int buf) {
        uint32_t Ab = As0 + buf*STG_BYTES;
        uint32_t Bb = Bs0 + buf*STG_BYTES;
        if (conv) {
            int kk = k0 >> cshift;
            int cb = k0 & (Cin - 1);
#pragma unroll
            for (int i = 0; i < 4; i++) {
                int id = tid + i*256;
                int row = id >> 3, ch = (id & 7)*8;
                int m = m0 + row;
                int b = m / LQ, l = m - b*LQ;
                int lp = l + kk - 1;
                int ok = (lp >= 0 && lp < LQ);
                cp16s(Ab + (uint32_t)(row*ASTRIDE + ch)*2,
                      &A[(long)(b*LQ + (ok ? lp : 0))*Cin + cb + ch], ok ? 16 : 0);
            }
        } else {
#pragma unroll
            for (int i = 0; i < 4; i++) {
                int id = tid + i*256;
                int row = id >> 3, ch = (id & 7)*8;
                cp16s(Ab + (uint32_t)(row*ASTRIDE + ch)*2,
                      &A[(long)(m0 + row)*K + k0 + ch], 16);
            }
        }
#pragma unroll
        for (int i = 0; i < 4; i++) {
            int id = tid + i*256;
            int row = id >> 3, ch = (id & 7)*8;
            cp16s(Bb + (uint32_t)(row*ASTRIDE + ch)*2,
                  &W[(long)(n0 + row)*K + k0 + ch], 16);
        }
    };

    auto compute = [&](int buf) {
        uint32_t Ab = As0 + buf*STG_BYTES;
        uint32_t Bb = Bs0 + buf*STG_BYTES;
#pragma unroll
        for (int ks = 0; ks < 4; ks++) {
            int kk = ks*16;
            unsigned a[2][4], b[8][2];
#pragma unroll
            for (int mi = 0; mi < 2; mi++)
                ldsm4(a[mi][0], a[mi][1], a[mi][2], a[mi][3],
                      Ab + (a_off[mi] + kk)*2);
#pragma unroll
            for (int p = 0; p < 4; p++) {
                unsigned r0, r1, r2, r3;
                ldsm4(r0, r1, r2, r3, Bb + (b_off[p] + kk)*2);
                b[2*p][0] = r0; b[2*p][1] = r1;
                b[2*p+1][0] = r2; b[2*p+1][1] = r3;
            }
#pragma unroll
            for (int mi = 0; mi < 2; mi++)
#pragma unroll
                for (int ni = 0; ni < 8; ni++)
                    mma_f16(acc[mi][ni], a[mi], b[ni]);
        }
    };

    loadP(0, 0);
    cp_commit();
    if (NP > 1) loadP(64, 1);
    cp_commit();

    for (int p = 0; p < NP; p++) {
        cp_wait1();
        __syncthreads();
        int pn = p + 2;
        if (pn < NP) loadP(pn << 6, pn % 3);
        cp_commit();
        compute(p % 3);
    }

    // ---- epilogue ----
#pragma unroll
    for (int mi = 0; mi < 2; mi++) {
        int r0 = m0 + wm*32 + mi*16 + g;
#pragma unroll
        for (int ni = 0; ni < 8; ni++) {
            int c0 = n0 + wn*64 + ni*8 + 2*t;
            float b0 = bias ? bias[c0] : 0.f;
            float b1 = bias ? bias[c0 + 1] : 0.f;
            float v0 = acc[mi][ni][0] + b0;
            float v1 = acc[mi][ni][1] + b1;
            float v2 = acc[mi][ni][2] + b0;
            float v3 = acc[mi][ni][3] + b1;
            if (resid) {
                v0 += resid[(long)r0*N + c0];
                v1 += resid[(long)r0*N + c0 + 1];
                v2 += resid[(long)(r0 + 8)*N + c0];
                v3 += resid[(long)(r0 + 8)*N + c0 + 1];
            }
            if (relu) {
                v0 = fmaxf(v0, 0.f); v1 = fmaxf(v1, 0.f);
                v2 = fmaxf(v2, 0.f); v3 = fmaxf(v3, 0.f);
            }
            if (Cf) {
                Cf[(long)r0*N + c0]           = v0;
                Cf[(long)r0*N + c0 + 1]       = v1;
                Cf[(long)(r0 + 8)*N + c0]     = v2;
                Cf[(long)(r0 + 8)*N + c0 + 1] = v3;
            } else {
                __half2 h01 = __floats2half2_rn(v0, v1);
                __half2 h23 = __floats2half2_rn(v2, v3);
                *(__half2*)&Ch[(long)r0*N + c0]       = h01;
                *(__half2*)&Ch[(long)(r0 + 8)*N + c0] = h23;
            }
        }
    }
}

// ---------------- ACT step pieces ----------------
__global__ void k_active_chk() {
    __shared__ int any;
    if (threadIdx.x == 0) any = 0;
    __syncthreads();
    int loc = 0;
    for (int i = threadIdx.x; i < BL; i += blockDim.x)
        if (g_hp[i] < THRESHV && g_nu[i] < (float)NLMAX) loc = 1;
    if (loc) atomicOr(&any, 1);
    __syncthreads();
    if (threadIdx.x == 0) g_active = any;
}

__global__ void k_builds_ln(int t, const float* __restrict__ pw, const float* __restrict__ pb,
                            const float* __restrict__ lng, const float* __restrict__ lnb) {
    if (!g_active) return;
    int row = blockIdx.x;
    int l = row % LQ;
    int c0 = threadIdx.x, c1 = threadIdx.x + 256;
    float v0 = g_state[row*HD + c0] + g_tsig[l*HD + c0] + g_psig[t*HD + c0];
    float v1 = g_state[row*HD + c1] + g_tsig[l*HD + c1] + g_psig[t*HD + c1];
    g_s[row*HD + c0] = v0;
    g_s[row*HD + c1] = v1;
    float dot = v0*pw[c0] + v1*pw[c1];
    float tot = blockReduceSum(dot);
    if (threadIdx.x == 0)
        g_pr[row] = 1.f / (1.f + expf(-(tot + pb[0])));
    float mu = blockReduceSum(v0 + v1) / (float)HD;
    float d0 = v0 - mu, d1 = v1 - mu;
    float var = blockReduceSum(d0*d0 + d1*d1) / (float)(HD - 1);
    float inv = 1.f / (sqrtf(var) + EPSV);
    g_xnh[row*HD + c0] = __float2half_rn(lng[c0]*d0*inv + lnb[c0]);
    g_xnh[row*HD + c1] = __float2half_rn(lng[c1]*d1*inv + lnb[c1]);
}

__global__ void k_ln(const float* __restrict__ X, const float* __restrict__ g,
                     const float* __restrict__ b, __half* __restrict__ Y) {
    if (!g_active) return;
    int row = blockIdx.x;
    const float* x = X + row*HD;
    int c0 = threadIdx.x, c1 = threadIdx.x + 256;
    float x0 = x[c0], x1 = x[c1];
    float mu = blockReduceSum(x0 + x1) / (float)HD;
    float d0 = x0 - mu, d1 = x1 - mu;
    float var = blockReduceSum(d0*d0 + d1*d1) / (float)(HD - 1);
    float inv = 1.f / (sqrtf(var) + EPSV);
    Y[row*HD + c0] = __float2half_rn(g[c0]*d0*inv + b[c0]);
    Y[row*HD + c1] = __float2half_rn(g[c1]*d1*inv + b[c1]);
}

__global__ void k_attn() {
    if (!g_active) return;
    int bh = blockIdx.x;
    int b = bh / NHEAD, h = bh % NHEAD;
    __shared__ float ks[LQ*65];
    __shared__ float vs[LQ*65];
    __shared__ float qrow[4][DKH];
    __shared__ float ps[4][LQ + 1];
    int tid = threadIdx.x;
    long qbase = (long)(b*LQ)*QKVN + h*DKH;
    for (int i = tid; i < LQ*DKH; i += 128) {
        int j = i / DKH, d = i % DKH;
        ks[j*65 + d] = __half2float(g_qkvh[qbase + 512 + (long)j*QKVN + d]);
        vs[j*65 + d] = __half2float(g_qkvh[qbase + 1024 + (long)j*QKVN + d]);
    }
    __syncthreads();
    int w = tid >> 5, lane = tid & 31;
    for (int r = w; r < LQ; r += 4) {
        for (int d = lane; d < DKH; d += 32)
            qrow[w][d] = __half2float(g_qkvh[qbase + (long)r*QKVN + d]);
        __syncwarp();
        float sc[3];
#pragma unroll
        for (int jj = 0; jj < 3; jj++) {
            int j = lane + jj*32;
            float a = -3.0e38f;
            if (j < LQ) {
                a = 0.f;
#pragma unroll
                for (int d = 0; d < DKH; d++) a += qrow[w][d]*ks[j*65 + d];
            }
            sc[jj] = a;
        }
        float mx = fmaxf(sc[0], fmaxf(sc[1], sc[2]));
#pragma unroll
        for (int o = 16; o; o >>= 1) mx = fmaxf(mx, __shfl_xor_sync(0xffffffffu, mx, o));
        float sum = 0.f;
#pragma unroll
        for (int jj = 0; jj < 3; jj++) {
            int j = lane + jj*32;
            float e = (j < LQ) ? expf(sc[jj] - mx) : 0.f;
            sc[jj] = e; sum += e;
        }
#pragma unroll
        for (int o = 16; o; o >>= 1) sum += __shfl_xor_sync(0xffffffffu, sum, o);
        float inv = 1.f / sum;
#pragma unroll
        for (int jj = 0; jj < 3; jj++) {
            int j = lane + jj*32;
            if (j < LQ) ps[w][j] = sc[jj]*inv;
        }
        __syncwarp();
        for (int d = lane; d < DKH; d += 32) {
            float a = 0.f;
#pragma unroll 8
            for (int j = 0; j < LQ; j++) a += ps[w][j]*vs[j*65 + d];
            g_ctxh[(long)(b*LQ)*HD + h*DKH + (long)r*HD + d] = __float2half_rn(a);
        }
        __syncwarp();
    }
}

__global__ void k_halt() {
    if (!g_active) return;
    int row = blockIdx.x;
    __shared__ float s_uw;
    if (threadIdx.x == 0) {
        float pr = g_pr[row], hp = g_hp[row], rem = g_rem[row], nu = g_nu[row];
        float still = (hp < 1.0f) ? 1.f : 0.f;
        float tot = hp + pr*still;
        float nh  = ((tot > THRESHV) ? 1.f : 0.f)*still;
        float st2 = ((tot <= THRESHV) ? 1.f : 0.f)*still;
        float hp2 = hp + pr*st2;
        float rem2 = rem + nh*(1.f - hp2);
        hp2 = hp2 + nh*rem2;
        float nu2 = nu + st2 + nh;
        float uw = pr*st2 + nh*rem2;
        g_hp[row] = hp2; g_rem[row] = rem2; g_nu[row] = nu2;
        s_uw = uw;
    }
    __syncthreads();
    float uw = s_uw;
    for (int c = threadIdx.x; c < HD; c += blockDim.x) {
        int i = row*HD + c;
        float y = g_y[i];
        g_prev[i]  = y*uw + g_prev[i]*(1.f - uw);
        g_state[i] = y;
    }
}

// ---------------- pooling / softmax / tail ----------------
__global__ void k_pool() {
    int b = blockIdx.x;
    for (int c = threadIdx.x; c < HD; c += blockDim.x) {
        float a = 0.f;
        for (int l = 0; l < LQ; l++) a += g_prev[(b*LQ + l)*HD + c];
        g_pooledh[b*HD + c] = __float2half_rn(a / (float)LQ);
    }
}

__global__ void k_softmax(float* __restrict__ out) {
    int b = blockIdx.x;
    const float* a = out + (long)b*VOC;
    float* sm = out + (long)BB*VOC + (long)b*VOC;
    float mx = -3.0e38f;
    for (int i = threadIdx.x; i < VOC; i += blockDim.x) mx = fmaxf(mx, a[i]);
    float M = blockReduceMax(mx);
    float s = 0.f;
    for (int i = threadIdx.x; i < VOC; i += blockDim.x) s += expf(a[i] - M);
    float S = blockReduceSum(s);
    float inv = 1.f / S;
    for (int i = threadIdx.x; i < VOC; i += blockDim.x) sm[i] = expf(a[i] - M)*inv;
}

__global__ void k_tail(float* __restrict__ out) {
    int i = blockIdx.x * blockDim.x + threadIdx.x;
    if (i < BL) {
        out[(long)2*BB*VOC + i]      = g_rem[i];
        out[(long)2*BB*VOC + BL + i] = g_nu[i];
    }
}

// ---------------- host ----------------
extern "C" void kernel_launch(void* const* d_in, const int* in_sizes, int n_in,
                              void* d_out, int out_size) {
    const int*   story = (const int*)d_in[0];
    const int*   query = (const int*)d_in[1];
    const float* emb   = (const float*)d_in[2];
    const float* mask  = (const float*)d_in[3];
    const float* projw = (const float*)d_in[4];
    const float* ln1g  = (const float*)d_in[5];
    const float* ln1b  = (const float*)d_in[6];
    const float* wq    = (const float*)d_in[7];
    const float* wk    = (const float*)d_in[8];
    const float* wv    = (const float*)d_in[9];
    const float* wo    = (const float*)d_in[10];
    const float* c1w   = (const float*)d_in[11];
    const float* c1b   = (const float*)d_in[12];
    const float* c2w   = (const float*)d_in[13];
    const float* c2b   = (const float*)d_in[14];
    const float* ln2g  = (const float*)d_in[15];
    const float* ln2b  = (const float*)d_in[16];
    const float* pw    = (const float*)d_in[17];
    const float* pb    = (const float*)d_in[18];
    const float* outb  = (const float*)d_in[19];
    float* out = (float*)d_out;

    void *p_state, *p_s, *p_s2, *p_y, *p_xh, *p_xnh, *p_xn2h, *p_qkvh, *p_ctxh,
         *p_midh, *p_pwt, *p_wot, *p_wqkvt, *p_w1t, *p_w2t, *p_embh, *p_pooledh;
    cudaGetSymbolAddress(&p_state, g_state);
    cudaGetSymbolAddress(&p_s, g_s);
    cudaGetSymbolAddress(&p_s2, g_s2);
    cudaGetSymbolAddress(&p_y, g_y);
    cudaGetSymbolAddress(&p_xh, g_xh);
    cudaGetSymbolAddress(&p_xnh, g_xnh);
    cudaGetSymbolAddress(&p_xn2h, g_xn2h);
    cudaGetSymbolAddress(&p_qkvh, g_qkvh);
    cudaGetSymbolAddress(&p_ctxh, g_ctxh);
    cudaGetSymbolAddress(&p_midh, g_midh);
    cudaGetSymbolAddress(&p_pwt, g_pwt);
    cudaGetSymbolAddress(&p_wot, g_wot);
    cudaGetSymbolAddress(&p_wqkvt, g_wqkvt);
    cudaGetSymbolAddress(&p_w1t, g_w1t);
    cudaGetSymbolAddress(&p_w2t, g_w2t);
    cudaGetSymbolAddress(&p_embh, g_embh);
    cudaGetSymbolAddress(&p_pooledh, g_pooledh);

    cudaFuncSetAttribute(k_gemm_h, cudaFuncAttributeMaxDynamicSharedMemorySize, SMEM_H);

    k_sigs<<<(LQ*HD + NLMAX*HD + 255)/256, 256>>>();
    k_w1t<<<(FSZ*3*HD + 255)/256, 256>>>(c1w);
    k_w2t<<<(HD*3*FSZ + 255)/256, 256>>>(c2w);
    k_wsq<<<(HD*HD + 255)/256, 256>>>(projw, wo);
    k_wqkv<<<(QKVN*HD + 255)/256, 256>>>(wq, wk, wv);
    k_embh<<<(VOC*HD + 255)/256, 256>>>(emb);
    k_init<<<(BL*HD + 255)/256, 256>>>();
    k_embed<<<BL, 128>>>(story, query, emb, mask);

    // state = x @ proj_w  (fp32 out)
    {
        dim3 grid(HD/128, BL/128);
        k_gemm_h<<<grid, 256, SMEM_H>>>((const __half*)p_xh, (const __half*)p_pwt,
                                        (float*)p_state, nullptr, BL, HD, HD,
                                        nullptr, nullptr, 0, 0, 0, 0, 0);
    }

    for (int t = 0; t < NLMAX; t++) {
        k_active_chk<<<1, 1024>>>();
        k_builds_ln<<<BL, 256>>>(t, pw, pb, ln1g, ln1b);
        {
            dim3 gq(QKVN/128, BL/128);
            k_gemm_h<<<gq, 256, SMEM_H>>>((const __half*)p_xnh, (const __half*)p_wqkvt,
                                          nullptr, (__half*)p_qkvh, BL, QKVN, HD,
                                          nullptr, nullptr, 0, 1, 0, 0, 0);
        }
        k_attn<<<BB*NHEAD, 128>>>();
        {
            dim3 go(HD/128, BL/128);
            k_gemm_h<<<go, 256, SMEM_H>>>((const __half*)p_ctxh, (const __half*)p_wot,
                                          (float*)p_s2, nullptr, BL, HD, HD,
                                          nullptr, (const float*)p_s, 0, 1, 0, 0, 0);
        }
        k_ln<<<BL, 256>>>((const float*)p_s2, ln2g, ln2b, (__half*)p_xn2h);
        {
            dim3 gc1(FSZ/128, BL/128);
            k_gemm_h<<<gc1, 256, SMEM_H>>>((const __half*)p_xn2h, (const __half*)p_w1t,
                                           nullptr, (__half*)p_midh, BL, FSZ, 3*HD,
                                           c1b, nullptr, 1, 1, 1, HD, 9);
        }
        {
            dim3 gc2(HD/128, BL/128);
            k_gemm_h<<<gc2, 256, SMEM_H>>>((const __half*)p_midh, (const __half*)p_w2t,
                                           (float*)p_y, nullptr, BL, HD, 3*FSZ,
                                           c2b, (const float*)p_s2, 0, 1, 1, FSZ, 11);
        }
        k_halt<<<BL, 256>>>();
    }

    k_pool<<<BB, 256>>>();
    // a_hat = pooled @ emb^T + out_b  (emb already [N][K])
    {
        dim3 grid(VOC/128, BB/128);
        k_gemm_h<<<grid, 256, SMEM_H>>>((const __half*)p_pooledh, (const __half*)p_embh,
                                        out, nullptr, BB, VOC, HD,
                                        outb, nullptr, 0, 0, 0, 0, 0);
    }
    k_softmax<<<BB, 1024>>>(out);
    k_tail<<<(BL + 255)/256, 256>>>(out);
}

// round 14
// speedup vs baseline: 1.7805x; 1.0614x over previous
#include <cuda_runtime.h>
#include <cuda_fp16.h>
#include <math.h>
#include <cstdint>

#define BB     256
#define MEMN   70
#define SLENQ  11
#define LQ     71
#define BL     (BB*LQ)       // 18176
#define HD     512
#define FSZ    2048
#define NHEAD  8
#define DKH    64
#define NLMAX  6
#define VOC    32000
#define QKVN   1536
#define THRESHV 0.9f
#define EPSV   1e-6f

// fp16 GEMM: 128x128 block, K-panel 64 halves, 3 stages, ldmatrix fragments
#define ASTRIDE 72
#define STG_HALVES (128*ASTRIDE)
#define STG_BYTES  (STG_HALVES*2)          // 18432
#define SMEM_H (3*2*STG_BYTES)             // 110592

// ---------------- scratch (device globals; no allocation) ----------------
__device__ float  g_state[BL*HD];
__device__ float  g_prev[BL*HD];
__device__ float  g_s[BL*HD];
__device__ float  g_s2[BL*HD];
__device__ __half g_xh[BL*HD];
__device__ __half g_xnh[BL*HD];
__device__ __half g_xn2h[BL*HD];
__device__ __half g_qkvh[BL*QKVN];
__device__ __half g_ctxh[BL*HD];
__device__ __half g_midh[BL*FSZ];
__device__ __half g_pwt[HD*HD];          // [N][K] proj_w^T
__device__ __half g_wot[HD*HD];          // [N][K] wo^T
__device__ __half g_wqkvt[QKVN*HD];      // [1536][512], q-scale baked
__device__ __half g_w1t[FSZ*3*HD];       // [2048][1536]
__device__ __half g_w2t[HD*3*FSZ];       // [512][6144]
__device__ __half g_embh[VOC*HD];        // [32000][512]
__device__ __half g_pooledh[BB*HD];
__device__ float  g_tsig[LQ*HD];
__device__ float  g_psig[NLMAX*HD];
__device__ float  g_hp[BL], g_rem[BL], g_nu[BL], g_pr[BL], g_uw[BL];
__device__ int    g_act[8];

// ---------------- helpers ----------------
__device__ __forceinline__ uint32_t smem_u32(const void* p) {
    uint32_t a;
    asm("{ .reg .u64 t; cvta.to.shared.u64 t, %1; cvt.u32.u64 %0, t; }" : "=r"(a) : "l"(p));
    return a;
}

__device__ __forceinline__ void mma_f16(float* d, const unsigned* a, const unsigned* b) {
    asm volatile(
        "mma.sync.aligned.m16n8k16.row.col.f32.f16.f16.f32 "
        "{%0,%1,%2,%3}, {%4,%5,%6,%7}, {%8,%9}, {%0,%1,%2,%3};"
        : "+f"(d[0]), "+f"(d[1]), "+f"(d[2]), "+f"(d[3])
        : "r"(a[0]), "r"(a[1]), "r"(a[2]), "r"(a[3]), "r"(b[0]), "r"(b[1]));
}

__device__ __forceinline__ void ldsm4(unsigned& r0, unsigned& r1, unsigned& r2, unsigned& r3,
                                      uint32_t addr) {
    asm volatile("ldmatrix.sync.aligned.m8n8.x4.shared.b16 {%0,%1,%2,%3}, [%4];"
                 : "=r"(r0), "=r"(r1), "=r"(r2), "=r"(r3) : "r"(addr));
}

__device__ __forceinline__ void cp16s(uint32_t daddr, const void* src, int ss) {
    asm volatile("cp.async.cg.shared.global [%0], [%1], 16, %2;"
                 :: "r"(daddr), "l"(src), "r"(ss));
}
__device__ __forceinline__ void cp_commit() { asm volatile("cp.async.commit_group;"); }
__device__ __forceinline__ void cp_wait1()  { asm volatile("cp.async.wait_group 1;"); }

__device__ __forceinline__ float blockReduceSum(float v) {
    __shared__ float sh[32];
    __shared__ float res;
    int lane = threadIdx.x & 31, wid = threadIdx.x >> 5;
#pragma unroll
    for (int o = 16; o; o >>= 1) v += __shfl_xor_sync(0xffffffffu, v, o);
    if (lane == 0) sh[wid] = v;
    __syncthreads();
    if (wid == 0) {
        float x = (lane < (int)(blockDim.x >> 5)) ? sh[lane] : 0.f;
#pragma unroll
        for (int o = 16; o; o >>= 1) x += __shfl_xor_sync(0xffffffffu, x, o);
        if (lane == 0) res = x;
    }
    __syncthreads();
    return res;
}

__device__ __forceinline__ float blockReduceMax(float v) {
    __shared__ float sh[32];
    __shared__ float res;
    int lane = threadIdx.x & 31, wid = threadIdx.x >> 5;
#pragma unroll
    for (int o = 16; o; o >>= 1) v = fmaxf(v, __shfl_xor_sync(0xffffffffu, v, o));
    if (lane == 0) sh[wid] = v;
    __syncthreads();
    if (wid == 0) {
        float x = (lane < (int)(blockDim.x >> 5)) ? sh[lane] : -3.0e38f;
#pragma unroll
        for (int o = 16; o; o >>= 1) x = fmaxf(x, __shfl_xor_sync(0xffffffffu, x, o));
        if (lane == 0) res = x;
    }
    __syncthreads();
    return res;
}

// ---------------- init / signals / weight prep ----------------
__global__ void k_init() {
    int i = blockIdx.x * blockDim.x + threadIdx.x;
    if (i < BL*HD) g_prev[i] = 0.f;
    if (i < BL) { g_hp[i] = 0.f; g_rem[i] = 0.f; g_nu[i] = 0.f; }
    if (i < 8) g_act[i] = (i == 0) ? 1 : 0;
}

__global__ void k_sigs() {
    int i = blockIdx.x * blockDim.x + threadIdx.x;
    const float log_inc = logf(1e4f) / 255.f;
    if (i < LQ*HD) {
        int pos = i / HD, c = i % HD;
        int j = (c < 256) ? c : c - 256;
        float val = (float)pos * expf(-log_inc * (float)j);
        g_tsig[i] = (c < 256) ? sinf(val) : cosf(val);
    } else {
        int k = i - LQ*HD;
        if (k < NLMAX*HD) {
            int pos = k / HD, c = k % HD;
            int j = (c < 256) ? c : c - 256;
            float val = (float)pos * expf(-log_inc * (float)j);
            g_psig[k] = (c < 256) ? sinf(val) : cosf(val);
        }
    }
}

__global__ void k_w1t(const float* __restrict__ w) {
    int i = blockIdx.x * blockDim.x + threadIdx.x;
    if (i < FSZ*3*HD) {
        int n = i / (3*HD), k = i % (3*HD);
        int kk = k / HD, c = k % HD;
        g_w1t[i] = __float2half_rn(w[(n*HD + c)*3 + kk]);
    }
}

__global__ void k_w2t(const float* __restrict__ w) {
    int i = blockIdx.x * blockDim.x + threadIdx.x;
    if (i < HD*3*FSZ) {
        int n = i / (3*FSZ), k = i % (3*FSZ);
        int kk = k / FSZ, c = k % FSZ;
        g_w2t[i] = __float2half_rn(w[(n*FSZ + c)*3 + kk]);
    }
}

__global__ void k_wsq(const float* __restrict__ projw, const float* __restrict__ wo) {
    int i = blockIdx.x * blockDim.x + threadIdx.x;
    if (i < HD*HD) {
        int n = i / HD, k = i % HD;
        g_pwt[i] = __float2half_rn(projw[k*HD + n]);
        g_wot[i] = __float2half_rn(wo[k*HD + n]);
    }
}

__global__ void k_wqkv(const float* __restrict__ wq, const float* __restrict__ wk,
                       const float* __restrict__ wv) {
    int i = blockIdx.x * blockDim.x + threadIdx.x;
    if (i < QKVN*HD) {
        int n = i / HD, k = i % HD;
        float v;
        if (n < 512)       v = 0.125f * wq[k*HD + n];
        else if (n < 1024) v = wk[k*HD + n - 512];
        else               v = wv[k*HD + n - 1024];
        g_wqkvt[i] = __float2half_rn(v);
    }
}

__global__ void k_embh(const float* __restrict__ emb) {
    long i = (long)blockIdx.x * blockDim.x + threadIdx.x;
    if (i < (long)VOC*HD) g_embh[i] = __float2half_rn(emb[i]);
}

__global__ void k_embed(const int* __restrict__ story, const int* __restrict__ query,
                        const float* __restrict__ emb, const float* __restrict__ mask) {
    int row = blockIdx.x;
    int b = row / LQ, m = row % LQ;
    for (int c = threadIdx.x; c < HD; c += blockDim.x) {
        float acc = 0.f;
        if (m < MEMN) {
#pragma unroll
            for (int s = 0; s < SLENQ; s++) {
                int tok = story[(b*MEMN + m)*SLENQ + s];
                acc += emb[(long)tok*HD + c] * mask[s*HD + c];
            }
        } else {
#pragma unroll
            for (int s = 0; s < SLENQ; s++) {
                int tok = query[b*SLENQ + s];
                acc += emb[(long)tok*HD + c] * mask[s*HD + c];
            }
        }
        g_xh[row*HD + c] = __float2half_rn(acc);
    }
}

// ============ fp16 GEMM: 128x128, K-panel 64, 3-stage cp.async, ldmatrix ============
// W is [N][K] half. C = act(A@W^T + bias + resid). conv: im2col gather on A.
// actidx >= 0: skip when g_act[actidx]==0. haltfuse: conv2 epilogue writes
// g_state = v and g_prev = v*uw + prev*(1-uw) instead of Cf/Ch.
__global__ void __launch_bounds__(256, 2)
k_gemm_h(const __half* __restrict__ A, const __half* __restrict__ W,
         float* __restrict__ Cf, __half* __restrict__ Ch,
         int M, int N, int K,
         const float* __restrict__ bias, const float* __restrict__ resid,
         int relu, int actidx, int conv, int Cin, int cshift, int haltfuse) {
    if (actidx >= 0 && !g_act[actidx]) return;
    extern __shared__ __half sm[];
    const uint32_t As0 = smem_u32(sm);                 // 3 stages A
    const uint32_t Bs0 = As0 + 3*STG_BYTES;            // 3 stages B

    const int tid = threadIdx.x;
    const int m0 = blockIdx.y * 128;
    const int n0 = blockIdx.x * 128;
    const int lane = tid & 31, wid = tid >> 5;
    const int wm = wid & 3, wn = wid >> 2;   // warp tile 32x64
    const int g = lane >> 2, t = lane & 3;
    const int sect = lane >> 3, lr = lane & 7;

    float acc[2][8][4];
#pragma unroll
    for (int mi = 0; mi < 2; mi++)
#pragma unroll
        for (int ni = 0; ni < 8; ni++)
#pragma unroll
            for (int j = 0; j < 4; j++) acc[mi][ni][j] = 0.f;

    // ldmatrix per-lane offsets (halves)
    uint32_t a_off[2], b_off[4];
#pragma unroll
    for (int mi = 0; mi < 2; mi++)
        a_off[mi] = (uint32_t)((wm*32 + mi*16 + (sect & 1)*8 + lr)*ASTRIDE + (sect >> 1)*8);
#pragma unroll
    for (int p = 0; p < 4; p++)
        b_off[p] = (uint32_t)((wn*64 + p*16 + (sect >> 1)*8 + lr)*ASTRIDE + (sect & 1)*8);

    const int NP = K >> 6;   // 64-half panels

    auto loadP = [&](int k0, int buf) {
        uint32_t Ab = As0 + buf*STG_BYTES;
        uint32_t Bb = Bs0 + buf*STG_BYTES;
        if (conv) {
            int kk = k0 >> cshift;
            int cb = k0 & (Cin - 1);
#pragma unroll
            for (int i = 0; i < 4; i++) {
                int id = tid + i*256;
                int row = id >> 3, ch = (id & 7)*8;
                int m = m0 + row;
                int b = m / LQ, l = m - b*LQ;
                int lp = l + kk - 1;
                int ok = (lp >= 0 && lp < LQ);
                cp16s(Ab + (uint32_t)(row*ASTRIDE + ch)*2,
                      &A[(long)(b*LQ + (ok ? lp : 0))*Cin + cb + ch], ok ? 16 : 0);
            }
        } else {
#pragma unroll
            for (int i = 0; i < 4; i++) {
                int id = tid + i*256;
                int row = id >> 3, ch = (id & 7)*8;
                cp16s(Ab + (uint32_t)(row*ASTRIDE + ch)*2,
                      &A[(long)(m0 + row)*K + k0 + ch], 16);
            }
        }
#pragma unroll
        for (int i = 0; i < 4; i++) {
            int id = tid + i*256;
            int row = id >> 3, ch = (id & 7)*8;
            cp16s(Bb + (uint32_t)(row*ASTRIDE + ch)*2,
                  &W[(long)(n0 + row)*K + k0 + ch], 16);
        }
    };

    auto compute = [&](int buf) {
        uint32_t Ab = As0 + buf*STG_BYTES;
        uint32_t Bb = Bs0 + buf*STG_BYTES;
#pragma unroll
        for (int ks = 0; ks < 4; ks++) {
            int kk = ks*16;
            unsigned a[2][4], b[8][2];
#pragma unroll
            for (int mi = 0; mi < 2; mi++)
                ldsm4(a[mi][0], a[mi][1], a[mi][2], a[mi][3],
                      Ab + (a_off[mi] + kk)*2);
#pragma unroll
            for (int p = 0; p < 4; p++) {
                unsigned r0, r1, r2, r3;
                ldsm4(r0, r1, r2, r3, Bb + (b_off[p] + kk)*2);
                b[2*p][0] = r0; b[2*p][1] = r1;
                b[2*p+1][0] = r2; b[2*p+1][1] = r3;
            }
#pragma unroll
            for (int mi = 0; mi < 2; mi++)
#pragma unroll
                for (int ni = 0; ni < 8; ni++)
                    mma_f16(acc[mi][ni], a[mi], b[ni]);
        }
    };

    loadP(0, 0);
    cp_commit();
    if (NP > 1) loadP(64, 1);
    cp_commit();

    for (int p = 0; p < NP; p++) {
        cp_wait1();
        __syncthreads();
        int pn = p + 2;
        if (pn < NP) loadP(pn << 6, pn % 3);
        cp_commit();
        compute(p % 3);
    }

    // ---- epilogue ----
#pragma unroll
    for (int mi = 0; mi < 2; mi++) {
        int r0 = m0 + wm*32 + mi*16 + g;
        float uw0 = 0.f, uw1 = 0.f;
        if (haltfuse) { uw0 = g_uw[r0]; uw1 = g_uw[r0 + 8]; }
#pragma unroll
        for (int ni = 0; ni < 8; ni++) {
            int c0 = n0 + wn*64 + ni*8 + 2*t;
            float b0 = bias ? bias[c0] : 0.f;
            float b1 = bias ? bias[c0 + 1] : 0.f;
            float v0 = acc[mi][ni][0] + b0;
            float v1 = acc[mi][ni][1] + b1;
            float v2 = acc[mi][ni][2] + b0;
            float v3 = acc[mi][ni][3] + b1;
            if (resid) {
                v0 += resid[(long)r0*N + c0];
                v1 += resid[(long)r0*N + c0 + 1];
                v2 += resid[(long)(r0 + 8)*N + c0];
                v3 += resid[(long)(r0 + 8)*N + c0 + 1];
            }
            if (relu) {
                v0 = fmaxf(v0, 0.f); v1 = fmaxf(v1, 0.f);
                v2 = fmaxf(v2, 0.f); v3 = fmaxf(v3, 0.f);
            }
            if (haltfuse) {
                long i00 = (long)r0*N + c0;
                long i10 = (long)(r0 + 8)*N + c0;
                g_state[i00]     = v0;
                g_state[i00 + 1] = v1;
                g_state[i10]     = v2;
                g_state[i10 + 1] = v3;
                g_prev[i00]     = v0*uw0 + g_prev[i00]*(1.f - uw0);
                g_prev[i00 + 1] = v1*uw0 + g_prev[i00 + 1]*(1.f - uw0);
                g_prev[i10]     = v2*uw1 + g_prev[i10]*(1.f - uw1);
                g_prev[i10 + 1] = v3*uw1 + g_prev[i10 + 1]*(1.f - uw1);
            } else if (Cf) {
                Cf[(long)r0*N + c0]           = v0;
                Cf[(long)r0*N + c0 + 1]       = v1;
                Cf[(long)(r0 + 8)*N + c0]     = v2;
                Cf[(long)(r0 + 8)*N + c0 + 1] = v3;
            } else {
                __half2 h01 = __floats2half2_rn(v0, v1);
                __half2 h23 = __floats2half2_rn(v2, v3);
                *(__half2*)&Ch[(long)r0*N + c0]       = h01;
                *(__half2*)&Ch[(long)(r0 + 8)*N + c0] = h23;
            }
        }
    }
}

// ---------------- ACT step pieces ----------------
// fused: build s (fp32), halting prob, LayerNorm1 -> xn (half)
__global__ void k_builds_ln(int t, const float* __restrict__ pw, const float* __restrict__ pb,
                            const float* __restrict__ lng, const float* __restrict__ lnb) {
    if (!g_act[t]) return;
    int row = blockIdx.x;
    int l = row % LQ;
    int c0 = threadIdx.x, c1 = threadIdx.x + 256;
    float v0 = g_state[row*HD + c0] + g_tsig[l*HD + c0] + g_psig[t*HD + c0];
    float v1 = g_state[row*HD + c1] + g_tsig[l*HD + c1] + g_psig[t*HD + c1];
    g_s[row*HD + c0] = v0;
    g_s[row*HD + c1] = v1;
    float dot = v0*pw[c0] + v1*pw[c1];
    float tot = blockReduceSum(dot);
    if (threadIdx.x == 0)
        g_pr[row] = 1.f / (1.f + expf(-(tot + pb[0])));
    float mu = blockReduceSum(v0 + v1) / (float)HD;
    float d0 = v0 - mu, d1 = v1 - mu;
    float var = blockReduceSum(d0*d0 + d1*d1) / (float)(HD - 1);
    float inv = 1.f / (sqrtf(var) + EPSV);
    g_xnh[row*HD + c0] = __float2half_rn(lng[c0]*d0*inv + lnb[c0]);
    g_xnh[row*HD + c1] = __float2half_rn(lng[c1]*d1*inv + lnb[c1]);
}

// halting state update + per-row update weight + next-step active flag
__global__ void k_haltp(int t) {
    if (!g_act[t]) return;
    int i = blockIdx.x * blockDim.x + threadIdx.x;
    if (i >= BL) return;
    float pr = g_pr[i], hp = g_hp[i], rem = g_rem[i], nu = g_nu[i];
    float still = (hp < 1.0f) ? 1.f : 0.f;
    float tot = hp + pr*still;
    float nh  = ((tot > THRESHV) ? 1.f : 0.f)*still;
    float st2 = ((tot <= THRESHV) ? 1.f : 0.f)*still;
    float hp2 = hp + pr*st2;
    float rem2 = rem + nh*(1.f - hp2);
    hp2 = hp2 + nh*rem2;
    float nu2 = nu + st2 + nh;
    float uw = pr*st2 + nh*rem2;
    g_hp[i] = hp2; g_rem[i] = rem2; g_nu[i] = nu2; g_uw[i] = uw;
    if (hp2 < THRESHV && nu2 < (float)NLMAX) g_act[t + 1] = 1;
}

__global__ void k_ln(int t, const float* __restrict__ X, const float* __restrict__ g,
                     const float* __restrict__ b, __half* __restrict__ Y) {
    if (!g_act[t]) return;
    int row = blockIdx.x;
    const float* x = X + row*HD;
    int c0 = threadIdx.x, c1 = threadIdx.x + 256;
    float x0 = x[c0], x1 = x[c1];
    float mu = blockReduceSum(x0 + x1) / (float)HD;
    float d0 = x0 - mu, d1 = x1 - mu;
    float var = blockReduceSum(d0*d0 + d1*d1) / (float)(HD - 1);
    float inv = 1.f / (sqrtf(var) + EPSV);
    Y[row*HD + c0] = __float2half_rn(g[c0]*d0*inv + b[c0]);
    Y[row*HD + c1] = __float2half_rn(g[c1]*d1*inv + b[c1]);
}

// attention over fused half qkv: q at col h*64, k at 512+h*64, v at 1024+h*64
#define KVS 68
__global__ void k_attn(int t) {
    if (!g_act[t]) return;
    int bh = blockIdx.x;
    int b = bh / NHEAD, h = bh % NHEAD;
    __shared__ float ks[LQ*KVS];
    __shared__ float vs[LQ*KVS];
    __shared__ float qrow[4][DKH];
    __shared__ float ps[4][72];
    int tid = threadIdx.x;
    long qbase = (long)(b*LQ)*QKVN + h*DKH;
    // stage K/V as fp32, stride 68, via half2 loads
    for (int i = tid; i < LQ*(DKH/2); i += 128) {
        int j = i / (DKH/2), d2 = (i % (DKH/2))*2;
        float2 kf = __half22float2(*(const __half2*)&g_qkvh[qbase + 512 + (long)j*QKVN + d2]);
        float2 vf = __half22float2(*(const __half2*)&g_qkvh[qbase + 1024 + (long)j*QKVN + d2]);
        ks[j*KVS + d2] = kf.x; ks[j*KVS + d2 + 1] = kf.y;
        vs[j*KVS + d2] = vf.x; vs[j*KVS + d2 + 1] = vf.y;
    }
    __syncthreads();
    int w = tid >> 5, lane = tid & 31;
    long ctxbase = (long)(b*LQ)*HD + h*DKH;
    for (int r = w; r < LQ; r += 4) {
        for (int d = lane; d < DKH; d += 32)
            qrow[w][d] = __half2float(g_qkvh[qbase + (long)r*QKVN + d]);
        __syncwarp();
        float sc[3];
#pragma unroll
        for (int jj = 0; jj < 3; jj++) {
            int j = lane + jj*32;
            float a = -3.0e38f;
            if (j < LQ) {
                a = 0.f;
#pragma unroll
                for (int d4 = 0; d4 < DKH; d4 += 4) {
                    float4 q4 = *(const float4*)&qrow[w][d4];
                    float4 k4 = *(const float4*)&ks[j*KVS + d4];
                    a += q4.x*k4.x; a += q4.y*k4.y;
                    a += q4.z*k4.z; a += q4.w*k4.w;
                }
            }
            sc[jj] = a;
        }
        float mx = fmaxf(sc[0], fmaxf(sc[1], sc[2]));
#pragma unroll
        for (int o = 16; o; o >>= 1) mx = fmaxf(mx, __shfl_xor_sync(0xffffffffu, mx, o));
        float sum = 0.f;
#pragma unroll
        for (int jj = 0; jj < 3; jj++) {
            int j = lane + jj*32;
            float e = (j < LQ) ? expf(sc[jj] - mx) : 0.f;
            sc[jj] = e; sum += e;
        }
#pragma unroll
        for (int o = 16; o; o >>= 1) sum += __shfl_xor_sync(0xffffffffu, sum, o);
        float inv = 1.f / sum;
#pragma unroll
        for (int jj = 0; jj < 3; jj++) {
            int j = lane + jj*32;
            if (j < LQ) ps[w][j] = sc[jj]*inv;
        }
        __syncwarp();
        {
            int d = lane*2;   // 0..62
            float ax = 0.f, ay = 0.f;
#pragma unroll 8
            for (int j = 0; j < LQ; j++) {
                float wp = ps[w][j];
                float2 v2 = *(const float2*)&vs[j*KVS + d];
                ax += wp*v2.x; ay += wp*v2.y;
            }
            *(__half2*)&g_ctxh[ctxbase + (long)r*HD + d] = __floats2half2_rn(ax, ay);
        }
        __syncwarp();
    }
}

// ---------------- pooling / softmax / tail ----------------
__global__ void k_pool() {
    int b = blockIdx.x;
    for (int c = threadIdx.x; c < HD; c += blockDim.x) {
        float a = 0.f;
        for (int l = 0; l < LQ; l++) a += g_prev[(b*LQ + l)*HD + c];
        g_pooledh[b*HD + c] = __float2half_rn(a / (float)LQ);
    }
}

__global__ void k_softmax(float* __restrict__ out) {
    int b = blockIdx.x;
    const float* a = out + (long)b*VOC;
    float* sm = out + (long)BB*VOC + (long)b*VOC;
    float mx = -3.0e38f;
    for (int i = threadIdx.x; i < VOC; i += blockDim.x) mx = fmaxf(mx, a[i]);
    float M = blockReduceMax(mx);
    float s = 0.f;
    for (int i = threadIdx.x; i < VOC; i += blockDim.x) s += expf(a[i] - M);
    float S = blockReduceSum(s);
    float inv = 1.f / S;
    for (int i = threadIdx.x; i < VOC; i += blockDim.x) sm[i] = expf(a[i] - M)*inv;
}

__global__ void k_tail(float* __restrict__ out) {
    int i = blockIdx.x * blockDim.x + threadIdx.x;
    if (i < BL) {
        out[(long)2*BB*VOC + i]      = g_rem[i];
        out[(long)2*BB*VOC + BL + i] = g_nu[i];
    }
}

// ---------------- host ----------------
extern "C" void kernel_launch(void* const* d_in, const int* in_sizes, int n_in,
                              void* d_out, int out_size) {
    const int*   story = (const int*)d_in[0];
    const int*   query = (const int*)d_in[1];
    const float* emb   = (const float*)d_in[2];
    const float* mask  = (const float*)d_in[3];
    const float* projw = (const float*)d_in[4];
    const float* ln1g  = (const float*)d_in[5];
    const float* ln1b  = (const float*)d_in[6];
    const float* wq    = (const float*)d_in[7];
    const float* wk    = (const float*)d_in[8];
    const float* wv    = (const float*)d_in[9];
    const float* wo    = (const float*)d_in[10];
    const float* c1w   = (const float*)d_in[11];
    const float* c1b   = (const float*)d_in[12];
    const float* c2w   = (const float*)d_in[13];
    const float* c2b   = (const float*)d_in[14];
    const float* ln2g  = (const float*)d_in[15];
    const float* ln2b  = (const float*)d_in[16];
    const float* pw    = (const float*)d_in[17];
    const float* pb    = (const float*)d_in[18];
    const float* outb  = (const float*)d_in[19];
    float* out = (float*)d_out;

    void *p_state, *p_s, *p_s2, *p_xh, *p_xnh, *p_xn2h, *p_qkvh, *p_ctxh,
         *p_midh, *p_pwt, *p_wot, *p_wqkvt, *p_w1t, *p_w2t, *p_embh, *p_pooledh;
    cudaGetSymbolAddress(&p_state, g_state);
    cudaGetSymbolAddress(&p_s, g_s);
    cudaGetSymbolAddress(&p_s2, g_s2);
    cudaGetSymbolAddress(&p_xh, g_xh);
    cudaGetSymbolAddress(&p_xnh, g_xnh);
    cudaGetSymbolAddress(&p_xn2h, g_xn2h);
    cudaGetSymbolAddress(&p_qkvh, g_qkvh);
    cudaGetSymbolAddress(&p_ctxh, g_ctxh);
    cudaGetSymbolAddress(&p_midh, g_midh);
    cudaGetSymbolAddress(&p_pwt, g_pwt);
    cudaGetSymbolAddress(&p_wot, g_wot);
    cudaGetSymbolAddress(&p_wqkvt, g_wqkvt);
    cudaGetSymbolAddress(&p_w1t, g_w1t);
    cudaGetSymbolAddress(&p_w2t, g_w2t);
    cudaGetSymbolAddress(&p_embh, g_embh);
    cudaGetSymbolAddress(&p_pooledh, g_pooledh);

    cudaFuncSetAttribute(k_gemm_h, cudaFuncAttributeMaxDynamicSharedMemorySize, SMEM_H);

    k_sigs<<<(LQ*HD + NLMAX*HD + 255)/256, 256>>>();
    k_w1t<<<(FSZ*3*HD + 255)/256, 256>>>(c1w);
    k_w2t<<<(HD*3*FSZ + 255)/256, 256>>>(c2w);
    k_wsq<<<(HD*HD + 255)/256, 256>>>(projw, wo);
    k_wqkv<<<(QKVN*HD + 255)/256, 256>>>(wq, wk, wv);
    k_embh<<<(VOC*HD + 255)/256, 256>>>(emb);
    k_init<<<(BL*HD + 255)/256, 256>>>();
    k_embed<<<BL, 128>>>(story, query, emb, mask);

    // state = x @ proj_w  (fp32 out)
    {
        dim3 grid(HD/128, BL/128);
        k_gemm_h<<<grid, 256, SMEM_H>>>((const __half*)p_xh, (const __half*)p_pwt,
                                        (float*)p_state, nullptr, BL, HD, HD,
                                        nullptr, nullptr, 0, -1, 0, 0, 0, 0);
    }

    for (int t = 0; t < NLMAX; t++) {
        k_builds_ln<<<BL, 256>>>(t, pw, pb, ln1g, ln1b);
        k_haltp<<<(BL + 255)/256, 256>>>(t);
        {
            dim3 gq(QKVN/128, BL/128);
            k_gemm_h<<<gq, 256, SMEM_H>>>((const __half*)p_xnh, (const __half*)p_wqkvt,
                                          nullptr, (__half*)p_qkvh, BL, QKVN, HD,
                                          nullptr, nullptr, 0, t, 0, 0, 0, 0);
        }
        k_attn<<<BB*NHEAD, 128>>>(t);
        {
            dim3 go(HD/128, BL/128);
            k_gemm_h<<<go, 256, SMEM_H>>>((const __half*)p_ctxh, (const __half*)p_wot,
                                          (float*)p_s2, nullptr, BL, HD, HD,
                                          nullptr, (const float*)p_s, 0, t, 0, 0, 0, 0);
        }
        k_ln<<<BL, 256>>>(t, (const float*)p_s2, ln2g, ln2b, (__half*)p_xn2h);
        {
            dim3 gc1(FSZ/128, BL/128);
            k_gemm_h<<<gc1, 256, SMEM_H>>>((const __half*)p_xn2h, (const __half*)p_w1t,
                                           nullptr, (__half*)p_midh, BL, FSZ, 3*HD,
                                           c1b, nullptr, 1, t, 1, HD, 9, 0);
        }
        {
            // conv2 + residual s2 + fused halting update (writes g_state/g_prev)
            dim3 gc2(HD/128, BL/128);
            k_gemm_h<<<gc2, 256, SMEM_H>>>((const __half*)p_midh, (const __half*)p_w2t,
                                           nullptr, nullptr, BL, HD, 3*FSZ,
                                           c2b, (const float*)p_s2, 0, t, 1, FSZ, 11, 1);
        }
    }

    k_pool<<<BB, 256>>>();
    // a_hat = pooled @ emb^T + out_b  (emb already [N][K])
    {
        dim3 grid(VOC/128, BB/128);
        k_gemm_h<<<grid, 256, SMEM_H>>>((const __half*)p_pooledh, (const __half*)p_embh,
                                        out, nullptr, BB, VOC, HD,
                                        outb, nullptr, 0, -1, 0, 0, 0, 0);
    }
    k_softmax<<<BB, 1024>>>(out);
    k_tail<<<(BL + 255)/256, 256>>>(out);
}

// round 15
// speedup vs baseline: 1.8164x; 1.0202x over previous
#include <cuda_runtime.h>
#include <cuda_fp16.h>
#include <math.h>
#include <cstdint>

#define BB     256
#define MEMN   70
#define SLENQ  11
#define LQ     71
#define LQP    73
#define PTOT   (BB*LQP)      // 18688
#define BL     (BB*LQ)       // 18176
#define HD     512
#define FSZ    2048
#define NHEAD  8
#define DKH    64
#define NLMAX  6
#define VOC    32000
#define QKVN   1536
#define THRESHV 0.9f
#define EPSV   1e-6f

// GEMM staging
#define ASTRIDE 72
#define STG_BYTES  (128*ASTRIDE*2)         // 18432
#define SMEM_H (3*2*STG_BYTES)             // 110592 (dense)
#define AROWS  134
#define ASTG_C (AROWS*ASTRIDE*2)           // 19296
#define SMEM_C (2*ASTG_C + 3*STG_BYTES)    // 93888 (conv)

// ---------------- scratch (device globals; no allocation) ----------------
__device__ float  g_state[BL*HD];
__device__ float  g_prev[BL*HD];
__device__ float  g_s[BL*HD];
__device__ float  g_s2[BL*HD];
__device__ __half g_xh[BL*HD];
__device__ __half g_xnh[BL*HD];
__device__ __half g_xn2hp[PTOT*HD];      // padded conv1 input
__device__ __half g_midhp[(long)PTOT*FSZ]; // padded conv2 input
__device__ __half g_qkvh[BL*QKVN];
__device__ __half g_ctxh[BL*HD];
__device__ __half g_pwt[HD*HD];          // [N][K] proj_w^T
__device__ __half g_wot[HD*HD];          // [N][K] wo^T
__device__ __half g_wqkvt[QKVN*HD];      // [1536][512], q-scale baked
__device__ __half g_w1t[FSZ*3*HD];       // [2048][1536]
__device__ __half g_w2t[HD*3*FSZ];       // [512][6144]
__device__ __half g_embh[VOC*HD];        // [32000][512]
__device__ __half g_pooledh[BB*HD];
__device__ float  g_tsig[LQ*HD];
__device__ float  g_psig[NLMAX*HD];
__device__ float  g_hp[BL], g_rem[BL], g_nu[BL], g_uw[BL];
__device__ int    g_act[8];

// ---------------- helpers ----------------
__device__ __forceinline__ uint32_t smem_u32(const void* p) {
    uint32_t a;
    asm("{ .reg .u64 t; cvta.to.shared.u64 t, %1; cvt.u32.u64 %0, t; }" : "=r"(a) : "l"(p));
    return a;
}

__device__ __forceinline__ void mma_f16(float* d, const unsigned* a, const unsigned* b) {
    asm volatile(
        "mma.sync.aligned.m16n8k16.row.col.f32.f16.f16.f32 "
        "{%0,%1,%2,%3}, {%4,%5,%6,%7}, {%8,%9}, {%0,%1,%2,%3};"
        : "+f"(d[0]), "+f"(d[1]), "+f"(d[2]), "+f"(d[3])
        : "r"(a[0]), "r"(a[1]), "r"(a[2]), "r"(a[3]), "r"(b[0]), "r"(b[1]));
}

__device__ __forceinline__ void ldsm4(unsigned& r0, unsigned& r1, unsigned& r2, unsigned& r3,
                                      uint32_t addr) {
    asm volatile("ldmatrix.sync.aligned.m8n8.x4.shared.b16 {%0,%1,%2,%3}, [%4];"
                 : "=r"(r0), "=r"(r1), "=r"(r2), "=r"(r3) : "r"(addr));
}

__device__ __forceinline__ void cp16s(uint32_t daddr, const void* src, int ss) {
    asm volatile("cp.async.cg.shared.global [%0], [%1], 16, %2;"
                 :: "r"(daddr), "l"(src), "r"(ss));
}
__device__ __forceinline__ void cp_commit() { asm volatile("cp.async.commit_group;"); }
__device__ __forceinline__ void cp_wait1()  { asm volatile("cp.async.wait_group 1;"); }

__device__ __forceinline__ float blockReduceSum(float v) {
    __shared__ float sh[32];
    __shared__ float res;
    int lane = threadIdx.x & 31, wid = threadIdx.x >> 5;
#pragma unroll
    for (int o = 16; o; o >>= 1) v += __shfl_xor_sync(0xffffffffu, v, o);
    if (lane == 0) sh[wid] = v;
    __syncthreads();
    if (wid == 0) {
        float x = (lane < (int)(blockDim.x >> 5)) ? sh[lane] : 0.f;
#pragma unroll
        for (int o = 16; o; o >>= 1) x += __shfl_xor_sync(0xffffffffu, x, o);
        if (lane == 0) res = x;
    }
    __syncthreads();
    return res;
}

__device__ __forceinline__ float blockReduceMax(float v) {
    __shared__ float sh[32];
    __shared__ float res;
    int lane = threadIdx.x & 31, wid = threadIdx.x >> 5;
#pragma unroll
    for (int o = 16; o; o >>= 1) v = fmaxf(v, __shfl_xor_sync(0xffffffffu, v, o));
    if (lane == 0) sh[wid] = v;
    __syncthreads();
    if (wid == 0) {
        float x = (lane < (int)(blockDim.x >> 5)) ? sh[lane] : -3.0e38f;
#pragma unroll
        for (int o = 16; o; o >>= 1) x = fmaxf(x, __shfl_xor_sync(0xffffffffu, x, o));
        if (lane == 0) res = x;
    }
    __syncthreads();
    return res;
}

// ---------------- init / signals / weight prep ----------------
__global__ void k_init() {
    int i = blockIdx.x * blockDim.x + threadIdx.x;
    if (i < BL*HD) g_prev[i] = 0.f;
    if (i < BL) { g_hp[i] = 0.f; g_rem[i] = 0.f; g_nu[i] = 0.f; }
    if (i < 8) g_act[i] = (i == 0) ? 1 : 0;
}

// zero the pad rows of the padded conv-input tensors
__global__ void k_zpad() {
    int i = blockIdx.x * blockDim.x + threadIdx.x;
    if (i < 512*FSZ) {
        int row = i / FSZ, c = i % FSZ;
        int b = row >> 1, side = row & 1;
        g_midhp[(long)(b*LQP + side*(LQP-1))*FSZ + c] = __float2half_rn(0.f);
    }
    if (i < 512*HD) {
        int row = i / HD, c = i % HD;
        int b = row >> 1, side = row & 1;
        g_xn2hp[(long)(b*LQP + side*(LQP-1))*HD + c] = __float2half_rn(0.f);
    }
}

__global__ void k_sigs() {
    int i = blockIdx.x * blockDim.x + threadIdx.x;
    const float log_inc = logf(1e4f) / 255.f;
    if (i < LQ*HD) {
        int pos = i / HD, c = i % HD;
        int j = (c < 256) ? c : c - 256;
        float val = (float)pos * expf(-log_inc * (float)j);
        g_tsig[i] = (c < 256) ? sinf(val) : cosf(val);
    } else {
        int k = i - LQ*HD;
        if (k < NLMAX*HD) {
            int pos = k / HD, c = k % HD;
            int j = (c < 256) ? c : c - 256;
            float val = (float)pos * expf(-log_inc * (float)j);
            g_psig[k] = (c < 256) ? sinf(val) : cosf(val);
        }
    }
}

__global__ void k_w1t(const float* __restrict__ w) {
    int i = blockIdx.x * blockDim.x + threadIdx.x;
    if (i < FSZ*3*HD) {
        int n = i / (3*HD), k = i % (3*HD);
        int kk = k / HD, c = k % HD;
        g_w1t[i] = __float2half_rn(w[(n*HD + c)*3 + kk]);
    }
}

__global__ void k_w2t(const float* __restrict__ w) {
    int i = blockIdx.x * blockDim.x + threadIdx.x;
    if (i < HD*3*FSZ) {
        int n = i / (3*FSZ), k = i % (3*FSZ);
        int kk = k / FSZ, c = k % FSZ;
        g_w2t[i] = __float2half_rn(w[(n*FSZ + c)*3 + kk]);
    }
}

__global__ void k_wsq(const float* __restrict__ projw, const float* __restrict__ wo) {
    int i = blockIdx.x * blockDim.x + threadIdx.x;
    if (i < HD*HD) {
        int n = i / HD, k = i % HD;
        g_pwt[i] = __float2half_rn(projw[k*HD + n]);
        g_wot[i] = __float2half_rn(wo[k*HD + n]);
    }
}

__global__ void k_wqkv(const float* __restrict__ wq, const float* __restrict__ wk,
                       const float* __restrict__ wv) {
    int i = blockIdx.x * blockDim.x + threadIdx.x;
    if (i < QKVN*HD) {
        int n = i / HD, k = i % HD;
        float v;
        if (n < 512)       v = 0.125f * wq[k*HD + n];
        else if (n < 1024) v = wk[k*HD + n - 512];
        else               v = wv[k*HD + n - 1024];
        g_wqkvt[i] = __float2half_rn(v);
    }
}

__global__ void k_embh(const float* __restrict__ emb) {
    long i = (long)blockIdx.x * blockDim.x + threadIdx.x;
    if (i < (long)VOC*HD) g_embh[i] = __float2half_rn(emb[i]);
}

__global__ void k_embed(const int* __restrict__ story, const int* __restrict__ query,
                        const float* __restrict__ emb, const float* __restrict__ mask) {
    int row = blockIdx.x;
    int b = row / LQ, m = row % LQ;
    for (int c = threadIdx.x; c < HD; c += blockDim.x) {
        float acc = 0.f;
        if (m < MEMN) {
#pragma unroll
            for (int s = 0; s < SLENQ; s++) {
                int tok = story[(b*MEMN + m)*SLENQ + s];
                acc += emb[(long)tok*HD + c] * mask[s*HD + c];
            }
        } else {
#pragma unroll
            for (int s = 0; s < SLENQ; s++) {
                int tok = query[b*SLENQ + s];
                acc += emb[(long)tok*HD + c] * mask[s*HD + c];
            }
        }
        g_xh[row*HD + c] = __float2half_rn(acc);
    }
}

// ============ dense fp16 GEMM: 128x128, K-panel 64, 3-stage, ldmatrix ============
__global__ void __launch_bounds__(256, 2)
k_gemm_h(const __half* __restrict__ A, const __half* __restrict__ W,
         float* __restrict__ Cf, __half* __restrict__ Ch,
         int M, int N, int K,
         const float* __restrict__ bias, const float* __restrict__ resid,
         int relu, int actidx) {
    if (actidx >= 0 && !g_act[actidx]) return;
    extern __shared__ __half sm[];
    const uint32_t As0 = smem_u32(sm);
    const uint32_t Bs0 = As0 + 3*STG_BYTES;

    const int tid = threadIdx.x;
    const int m0 = blockIdx.y * 128;
    const int n0 = blockIdx.x * 128;
    const int lane = tid & 31, wid = tid >> 5;
    const int wm = wid & 3, wn = wid >> 2;
    const int g = lane >> 2, t = lane & 3;
    const int sect = lane >> 3, lr = lane & 7;

    float acc[2][8][4];
#pragma unroll
    for (int mi = 0; mi < 2; mi++)
#pragma unroll
        for (int ni = 0; ni < 8; ni++)
#pragma unroll
            for (int j = 0; j < 4; j++) acc[mi][ni][j] = 0.f;

    uint32_t a_off[2], b_off[4];
#pragma unroll
    for (int mi = 0; mi < 2; mi++)
        a_off[mi] = (uint32_t)((wm*32 + mi*16 + (sect & 1)*8 + lr)*ASTRIDE + (sect >> 1)*8);
#pragma unroll
    for (int p = 0; p < 4; p++)
        b_off[p] = (uint32_t)((wn*64 + p*16 + (sect >> 1)*8 + lr)*ASTRIDE + (sect & 1)*8);

    const int NP = K >> 6;

    auto loadP = [&](int k0, int buf) {
        uint32_t Ab = As0 + buf*STG_BYTES;
        uint32_t Bb = Bs0 + buf*STG_BYTES;
#pragma unroll
        for (int i = 0; i < 4; i++) {
            int id = tid + i*256;
            int row = id >> 3, ch = (id & 7)*8;
            cp16s(Ab + (uint32_t)(row*ASTRIDE + ch)*2,
                  &A[(long)(m0 + row)*K + k0 + ch], 16);
        }
#pragma unroll
        for (int i = 0; i < 4; i++) {
            int id = tid + i*256;
            int row = id >> 3, ch = (id & 7)*8;
            cp16s(Bb + (uint32_t)(row*ASTRIDE + ch)*2,
                  &W[(long)(n0 + row)*K + k0 + ch], 16);
        }
    };

    auto compute = [&](int buf) {
        uint32_t Ab = As0 + buf*STG_BYTES;
        uint32_t Bb = Bs0 + buf*STG_BYTES;
#pragma unroll
        for (int ks = 0; ks < 4; ks++) {
            int kk = ks*16;
            unsigned a[2][4], b[8][2];
#pragma unroll
            for (int mi = 0; mi < 2; mi++)
                ldsm4(a[mi][0], a[mi][1], a[mi][2], a[mi][3], Ab + (a_off[mi] + kk)*2);
#pragma unroll
            for (int p = 0; p < 4; p++) {
                unsigned r0, r1, r2, r3;
                ldsm4(r0, r1, r2, r3, Bb + (b_off[p] + kk)*2);
                b[2*p][0] = r0; b[2*p][1] = r1;
                b[2*p+1][0] = r2; b[2*p+1][1] = r3;
            }
#pragma unroll
            for (int mi = 0; mi < 2; mi++)
#pragma unroll
                for (int ni = 0; ni < 8; ni++)
                    mma_f16(acc[mi][ni], a[mi], b[ni]);
        }
    };

    loadP(0, 0);
    cp_commit();
    if (NP > 1) loadP(64, 1);
    cp_commit();

    for (int p = 0; p < NP; p++) {
        cp_wait1();
        __syncthreads();
        int pn = p + 2;
        if (pn < NP) loadP(pn << 6, pn % 3);
        cp_commit();
        compute(p % 3);
    }

#pragma unroll
    for (int mi = 0; mi < 2; mi++) {
        int r0 = m0 + wm*32 + mi*16 + g;
#pragma unroll
        for (int ni = 0; ni < 8; ni++) {
            int c0 = n0 + wn*64 + ni*8 + 2*t;
            float b0 = bias ? bias[c0] : 0.f;
            float b1 = bias ? bias[c0 + 1] : 0.f;
            float v0 = acc[mi][ni][0] + b0;
            float v1 = acc[mi][ni][1] + b1;
            float v2 = acc[mi][ni][2] + b0;
            float v3 = acc[mi][ni][3] + b1;
            if (resid) {
                v0 += resid[(long)r0*N + c0];
                v1 += resid[(long)r0*N + c0 + 1];
                v2 += resid[(long)(r0 + 8)*N + c0];
                v3 += resid[(long)(r0 + 8)*N + c0 + 1];
            }
            if (relu) {
                v0 = fmaxf(v0, 0.f); v1 = fmaxf(v1, 0.f);
                v2 = fmaxf(v2, 0.f); v3 = fmaxf(v3, 0.f);
            }
            if (Cf) {
                Cf[(long)r0*N + c0]           = v0;
                Cf[(long)r0*N + c0 + 1]       = v1;
                Cf[(long)(r0 + 8)*N + c0]     = v2;
                Cf[(long)(r0 + 8)*N + c0 + 1] = v3;
            } else {
                __half2 h01 = __floats2half2_rn(v0, v1);
                __half2 h23 = __floats2half2_rn(v2, v3);
                *(__half2*)&Ch[(long)r0*N + c0]       = h01;
                *(__half2*)&Ch[(long)(r0 + 8)*N + c0] = h23;
            }
        }
    }
}

// ============ conv fp16 GEMM over padded input: A shared across 3 taps ============
// A: padded [PTOT][Cin]; W: [N][3*Cin]. Output either Chp (padded [PTOT][N]) or
// haltfuse (g_state/g_prev dense).
__global__ void __launch_bounds__(256, 2)
k_conv_h(const __half* __restrict__ A, const __half* __restrict__ W,
         __half* __restrict__ Chp, int N, int Cin,
         const float* __restrict__ bias, const float* __restrict__ resid,
         int relu, int actidx, int haltfuse) {
    if (!g_act[actidx]) return;
    extern __shared__ __half sm[];
    const uint32_t As0 = smem_u32(sm);                 // 2 stages x ASTG_C
    const uint32_t Bs0 = As0 + 2*ASTG_C;               // 3 stages x STG_BYTES

    const int tid = threadIdx.x;
    const int m0 = blockIdx.y * 128;
    const int n0 = blockIdx.x * 128;
    const int lane = tid & 31, wid = tid >> 5;
    const int wm = wid & 3, wn = wid >> 2;
    const int g = lane >> 2, t = lane & 3;
    const int sect = lane >> 3, lr = lane & 7;
    const int Kfull = 3*Cin;

    float acc[2][8][4];
#pragma unroll
    for (int mi = 0; mi < 2; mi++)
#pragma unroll
        for (int ni = 0; ni < 8; ni++)
#pragma unroll
            for (int j = 0; j < 4; j++) acc[mi][ni][j] = 0.f;

    const int b0 = m0 / LQ;
    const int pw0 = b0*LQP + (m0 - b0*LQ);

    // per-lane A padded-row offsets (relative to window)
    int prel[2];
#pragma unroll
    for (int mi = 0; mi < 2; mi++) {
        int rowm = m0 + wm*32 + mi*16 + (sect & 1)*8 + lr;
        int bb = rowm / LQ;
        prel[mi] = bb*LQP + (rowm - bb*LQ) - pw0;
    }
    const int acol = (sect >> 1)*8;

    uint32_t b_off[4];
#pragma unroll
    for (int p = 0; p < 4; p++)
        b_off[p] = (uint32_t)((wn*64 + p*16 + (sect >> 1)*8 + lr)*ASTRIDE + (sect & 1)*8);

    const int ncp = Cin >> 6;
    const int NV = 3*ncp;

    auto loadA = [&](int c, int buf) {
        uint32_t Ab = As0 + buf*ASTG_C;
        int cb = c*64;
        for (int i = tid; i < AROWS*8; i += 256) {
            int row = i >> 3, ch = (i & 7)*8;
            int gidx = pw0 + row;
            int ok = (gidx < PTOT);
            cp16s(Ab + (uint32_t)(row*ASTRIDE + ch)*2,
                  &A[(long)(ok ? gidx : 0)*Cin + cb + ch], ok ? 16 : 0);
        }
    };

    auto loadB = [&](int v, int buf) {
        uint32_t Bb = Bs0 + buf*STG_BYTES;
        int kk = v % 3, c = v / 3;
        int kcol = kk*Cin + c*64;
#pragma unroll
        for (int i = 0; i < 4; i++) {
            int id = tid + i*256;
            int row = id >> 3, ch = (id & 7)*8;
            cp16s(Bb + (uint32_t)(row*ASTRIDE + ch)*2,
                  &W[(long)(n0 + row)*Kfull + kcol + ch], 16);
        }
    };

    auto compute = [&](int v) {
        int kk = v % 3;
        uint32_t Ab = As0 + ((v/3) & 1)*ASTG_C;
        uint32_t Bb = Bs0 + (v % 3)*STG_BYTES;
#pragma unroll
        for (int ks = 0; ks < 4; ks++) {
            int kc = ks*16;
            unsigned a[2][4], b[8][2];
#pragma unroll
            for (int mi = 0; mi < 2; mi++)
                ldsm4(a[mi][0], a[mi][1], a[mi][2], a[mi][3],
                      Ab + (uint32_t)((prel[mi] + kk)*ASTRIDE + acol + kc)*2);
#pragma unroll
            for (int p = 0; p < 4; p++) {
                unsigned r0, r1, r2, r3;
                ldsm4(r0, r1, r2, r3, Bb + (b_off[p] + kc)*2);
                b[2*p][0] = r0; b[2*p][1] = r1;
                b[2*p+1][0] = r2; b[2*p+1][1] = r3;
            }
#pragma unroll
            for (int mi = 0; mi < 2; mi++)
#pragma unroll
                for (int ni = 0; ni < 8; ni++)
                    mma_f16(acc[mi][ni], a[mi], b[ni]);
        }
    };

    // prologue: group0 = A(0)+B(0); group1 = B(1)
    loadA(0, 0);
    loadB(0, 0);
    cp_commit();
    if (NV > 1) loadB(1, 1);
    cp_commit();

    for (int v = 0; v < NV; v++) {
        cp_wait1();
        __syncthreads();
        int vv = v + 2;
        if (vv < NV) {
            loadB(vv, vv % 3);
            if (vv % 3 == 2) {
                int c = (vv + 1)/3;
                if (c < ncp) loadA(c, c & 1);
            }
        }
        cp_commit();
        compute(v);
    }

    // ---- epilogue ----
#pragma unroll
    for (int mi = 0; mi < 2; mi++) {
        int r0 = m0 + wm*32 + mi*16 + g;
        float uw0 = 0.f, uw1 = 0.f;
        if (haltfuse) { uw0 = g_uw[r0]; uw1 = g_uw[r0 + 8]; }
#pragma unroll
        for (int ni = 0; ni < 8; ni++) {
            int c0 = n0 + wn*64 + ni*8 + 2*t;
            float b0 = bias[c0], b1 = bias[c0 + 1];
            float v0 = acc[mi][ni][0] + b0;
            float v1 = acc[mi][ni][1] + b1;
            float v2 = acc[mi][ni][2] + b0;
            float v3 = acc[mi][ni][3] + b1;
            if (resid) {
                v0 += resid[(long)r0*N + c0];
                v1 += resid[(long)r0*N + c0 + 1];
                v2 += resid[(long)(r0 + 8)*N + c0];
                v3 += resid[(long)(r0 + 8)*N + c0 + 1];
            }
            if (relu) {
                v0 = fmaxf(v0, 0.f); v1 = fmaxf(v1, 0.f);
                v2 = fmaxf(v2, 0.f); v3 = fmaxf(v3, 0.f);
            }
            if (haltfuse) {
                long i00 = (long)r0*N + c0;
                long i10 = (long)(r0 + 8)*N + c0;
                g_state[i00]     = v0;
                g_state[i00 + 1] = v1;
                g_state[i10]     = v2;
                g_state[i10 + 1] = v3;
                g_prev[i00]     = v0*uw0 + g_prev[i00]*(1.f - uw0);
                g_prev[i00 + 1] = v1*uw0 + g_prev[i00 + 1]*(1.f - uw0);
                g_prev[i10]     = v2*uw1 + g_prev[i10]*(1.f - uw1);
                g_prev[i10 + 1] = v3*uw1 + g_prev[i10 + 1]*(1.f - uw1);
            } else {
                int ba = r0 / LQ, bb = (r0 + 8) / LQ;
                long p0 = (long)(ba*LQP + 1 + (r0 - ba*LQ))*N + c0;
                long p1 = (long)(bb*LQP + 1 + (r0 + 8 - bb*LQ))*N + c0;
                __half2 h01 = __floats2half2_rn(v0, v1);
                __half2 h23 = __floats2half2_rn(v2, v3);
                *(__half2*)&Chp[p0] = h01;
                *(__half2*)&Chp[p1] = h23;
            }
        }
    }
}

// ---------------- ACT step pieces ----------------
// fused: build s (fp32), halting prob + halting state update, LayerNorm1 -> xnh
__global__ void k_builds_ln(int t, const float* __restrict__ pw, const float* __restrict__ pb,
                            const float* __restrict__ lng, const float* __restrict__ lnb) {
    if (!g_act[t]) return;
    int row = blockIdx.x;
    int l = row % LQ;
    int c0 = threadIdx.x, c1 = threadIdx.x + 256;
    float v0 = g_state[row*HD + c0] + g_tsig[l*HD + c0] + g_psig[t*HD + c0];
    float v1 = g_state[row*HD + c1] + g_tsig[l*HD + c1] + g_psig[t*HD + c1];
    g_s[row*HD + c0] = v0;
    g_s[row*HD + c1] = v1;
    float dot = v0*pw[c0] + v1*pw[c1];
    float tot = blockReduceSum(dot);
    if (threadIdx.x == 0) {
        float pr = 1.f / (1.f + expf(-(tot + pb[0])));
        float hp = g_hp[row], rem = g_rem[row], nu = g_nu[row];
        float still = (hp < 1.0f) ? 1.f : 0.f;
        float tt = hp + pr*still;
        float nh  = ((tt > THRESHV) ? 1.f : 0.f)*still;
        float st2 = ((tt <= THRESHV) ? 1.f : 0.f)*still;
        float hp2 = hp + pr*st2;
        float rem2 = rem + nh*(1.f - hp2);
        hp2 = hp2 + nh*rem2;
        float nu2 = nu + st2 + nh;
        float uw = pr*st2 + nh*rem2;
        g_hp[row] = hp2; g_rem[row] = rem2; g_nu[row] = nu2; g_uw[row] = uw;
        if (hp2 < THRESHV && nu2 < (float)NLMAX) g_act[t + 1] = 1;
    }
    float mu = blockReduceSum(v0 + v1) / (float)HD;
    float d0 = v0 - mu, d1 = v1 - mu;
    float var = blockReduceSum(d0*d0 + d1*d1) / (float)(HD - 1);
    float inv = 1.f / (sqrtf(var) + EPSV);
    g_xnh[row*HD + c0] = __float2half_rn(lng[c0]*d0*inv + lnb[c0]);
    g_xnh[row*HD + c1] = __float2half_rn(lng[c1]*d1*inv + lnb[c1]);
}

// LayerNorm2: fp32 in (s2), half out to PADDED xn2hp
__global__ void k_ln(int t, const float* __restrict__ X, const float* __restrict__ g,
                     const float* __restrict__ b) {
    if (!g_act[t]) return;
    int row = blockIdx.x;
    int bb = row / LQ;
    long prow = (long)(bb*LQP + 1 + (row - bb*LQ));
    const float* x = X + row*HD;
    int c0 = threadIdx.x, c1 = threadIdx.x + 256;
    float x0 = x[c0], x1 = x[c1];
    float mu = blockReduceSum(x0 + x1) / (float)HD;
    float d0 = x0 - mu, d1 = x1 - mu;
    float var = blockReduceSum(d0*d0 + d1*d1) / (float)(HD - 1);
    float inv = 1.f / (sqrtf(var) + EPSV);
    g_xn2hp[prow*HD + c0] = __float2half_rn(g[c0]*d0*inv + b[c0]);
    g_xn2hp[prow*HD + c1] = __float2half_rn(g[c1]*d1*inv + b[c1]);
}

// attention (256 threads): q at col h*64, k at 512+h*64, v at 1024+h*64
#define KVS 68
__global__ void k_attn(int t) {
    if (!g_act[t]) return;
    int bh = blockIdx.x;
    int b = bh / NHEAD, h = bh % NHEAD;
    __shared__ float ks[LQ*KVS];
    __shared__ float vs[LQ*KVS];
    __shared__ float qrow[8][DKH];
    __shared__ float ps[8][72];
    int tid = threadIdx.x;
    long qbase = (long)(b*LQ)*QKVN + h*DKH;
    for (int i = tid; i < LQ*(DKH/2); i += 256) {
        int j = i / (DKH/2), d2 = (i % (DKH/2))*2;
        float2 kf = __half22float2(*(const __half2*)&g_qkvh[qbase + 512 + (long)j*QKVN + d2]);
        float2 vf = __half22float2(*(const __half2*)&g_qkvh[qbase + 1024 + (long)j*QKVN + d2]);
        ks[j*KVS + d2] = kf.x; ks[j*KVS + d2 + 1] = kf.y;
        vs[j*KVS + d2] = vf.x; vs[j*KVS + d2 + 1] = vf.y;
    }
    __syncthreads();
    int w = tid >> 5, lane = tid & 31;
    long ctxbase = (long)(b*LQ)*HD + h*DKH;
    for (int r = w; r < LQ; r += 8) {
        for (int d = lane; d < DKH; d += 32)
            qrow[w][d] = __half2float(g_qkvh[qbase + (long)r*QKVN + d]);
        __syncwarp();
        float sc[3];
#pragma unroll
        for (int jj = 0; jj < 3; jj++) {
            int j = lane + jj*32;
            float a = -3.0e38f;
            if (j < LQ) {
                a = 0.f;
#pragma unroll
                for (int d4 = 0; d4 < DKH; d4 += 4) {
                    float4 q4 = *(const float4*)&qrow[w][d4];
                    float4 k4 = *(const float4*)&ks[j*KVS + d4];
                    a += q4.x*k4.x; a += q4.y*k4.y;
                    a += q4.z*k4.z; a += q4.w*k4.w;
                }
            }
            sc[jj] = a;
        }
        float mx = fmaxf(sc[0], fmaxf(sc[1], sc[2]));
#pragma unroll
        for (int o = 16; o; o >>= 1) mx = fmaxf(mx, __shfl_xor_sync(0xffffffffu, mx, o));
        float sum = 0.f;
#pragma unroll
        for (int jj = 0; jj < 3; jj++) {
            int j = lane + jj*32;
            float e = (j < LQ) ? expf(sc[jj] - mx) : 0.f;
            sc[jj] = e; sum += e;
        }
#pragma unroll
        for (int o = 16; o; o >>= 1) sum += __shfl_xor_sync(0xffffffffu, sum, o);
        float inv = 1.f / sum;
#pragma unroll
        for (int jj = 0; jj < 3; jj++) {
            int j = lane + jj*32;
            if (j < LQ) ps[w][j] = sc[jj]*inv;
        }
        __syncwarp();
        {
            int d = lane*2;
            float ax = 0.f, ay = 0.f;
#pragma unroll 8
            for (int j = 0; j < LQ; j++) {
                float wp = ps[w][j];
                float2 v2 = *(const float2*)&vs[j*KVS + d];
                ax += wp*v2.x; ay += wp*v2.y;
            }
            *(__half2*)&g_ctxh[ctxbase + (long)r*HD + d] = __floats2half2_rn(ax, ay);
        }
        __syncwarp();
    }
}

// ---------------- pooling / softmax / tail ----------------
__global__ void k_pool() {
    int b = blockIdx.x;
    for (int c = threadIdx.x; c < HD; c += blockDim.x) {
        float a = 0.f;
        for (int l = 0; l < LQ; l++) a += g_prev[(b*LQ + l)*HD + c];
        g_pooledh[b*HD + c] = __float2half_rn(a / (float)LQ);
    }
}

__global__ void k_softmax(float* __restrict__ out) {
    int b = blockIdx.x;
    const float* a = out + (long)b*VOC;
    float* sm = out + (long)BB*VOC + (long)b*VOC;
    float mx = -3.0e38f;
    for (int i = threadIdx.x; i < VOC; i += blockDim.x) mx = fmaxf(mx, a[i]);
    float M = blockReduceMax(mx);
    float s = 0.f;
    for (int i = threadIdx.x; i < VOC; i += blockDim.x) s += expf(a[i] - M);
    float S = blockReduceSum(s);
    float inv = 1.f / S;
    for (int i = threadIdx.x; i < VOC; i += blockDim.x) sm[i] = expf(a[i] - M)*inv;
}

__global__ void k_tail(float* __restrict__ out) {
    int i = blockIdx.x * blockDim.x + threadIdx.x;
    if (i < BL) {
        out[(long)2*BB*VOC + i]      = g_rem[i];
        out[(long)2*BB*VOC + BL + i] = g_nu[i];
    }
}

// ---------------- host ----------------
extern "C" void kernel_launch(void* const* d_in, const int* in_sizes, int n_in,
                              void* d_out, int out_size) {
    const int*   story = (const int*)d_in[0];
    const int*   query = (const int*)d_in[1];
    const float* emb   = (const float*)d_in[2];
    const float* mask  = (const float*)d_in[3];
    const float* projw = (const float*)d_in[4];
    const float* ln1g  = (const float*)d_in[5];
    const float* ln1b  = (const float*)d_in[6];
    const float* wq    = (const float*)d_in[7];
    const float* wk    = (const float*)d_in[8];
    const float* wv    = (const float*)d_in[9];
    const float* wo    = (const float*)d_in[10];
    const float* c1w   = (const float*)d_in[11];
    const float* c1b   = (const float*)d_in[12];
    const float* c2w   = (const float*)d_in[13];
    const float* c2b   = (const float*)d_in[14];
    const float* ln2g  = (const float*)d_in[15];
    const float* ln2b  = (const float*)d_in[16];
    const float* pw    = (const float*)d_in[17];
    const float* pb    = (const float*)d_in[18];
    const float* outb  = (const float*)d_in[19];
    float* out = (float*)d_out;

    void *p_state, *p_s, *p_s2, *p_xh, *p_xnh, *p_xn2hp, *p_qkvh, *p_ctxh,
         *p_midhp, *p_pwt, *p_wot, *p_wqkvt, *p_w1t, *p_w2t, *p_embh, *p_pooledh;
    cudaGetSymbolAddress(&p_state, g_state);
    cudaGetSymbolAddress(&p_s, g_s);
    cudaGetSymbolAddress(&p_s2, g_s2);
    cudaGetSymbolAddress(&p_xh, g_xh);
    cudaGetSymbolAddress(&p_xnh, g_xnh);
    cudaGetSymbolAddress(&p_xn2hp, g_xn2hp);
    cudaGetSymbolAddress(&p_qkvh, g_qkvh);
    cudaGetSymbolAddress(&p_ctxh, g_ctxh);
    cudaGetSymbolAddress(&p_midhp, g_midhp);
    cudaGetSymbolAddress(&p_pwt, g_pwt);
    cudaGetSymbolAddress(&p_wot, g_wot);
    cudaGetSymbolAddress(&p_wqkvt, g_wqkvt);
    cudaGetSymbolAddress(&p_w1t, g_w1t);
    cudaGetSymbolAddress(&p_w2t, g_w2t);
    cudaGetSymbolAddress(&p_embh, g_embh);
    cudaGetSymbolAddress(&p_pooledh, g_pooledh);

    cudaFuncSetAttribute(k_gemm_h, cudaFuncAttributeMaxDynamicSharedMemorySize, SMEM_H);
    cudaFuncSetAttribute(k_conv_h, cudaFuncAttributeMaxDynamicSharedMemorySize, SMEM_C);

    k_sigs<<<(LQ*HD + NLMAX*HD + 255)/256, 256>>>();
    k_w1t<<<(FSZ*3*HD + 255)/256, 256>>>(c1w);
    k_w2t<<<(HD*3*FSZ + 255)/256, 256>>>(c2w);
    k_wsq<<<(HD*HD + 255)/256, 256>>>(projw, wo);
    k_wqkv<<<(QKVN*HD + 255)/256, 256>>>(wq, wk, wv);
    k_embh<<<(VOC*HD + 255)/256, 256>>>(emb);
    k_init<<<(BL*HD + 255)/256, 256>>>();
    k_zpad<<<(512*FSZ + 255)/256, 256>>>();
    k_embed<<<BL, 128>>>(story, query, emb, mask);

    // state = x @ proj_w  (fp32 out)
    {
        dim3 grid(HD/128, BL/128);
        k_gemm_h<<<grid, 256, SMEM_H>>>((const __half*)p_xh, (const __half*)p_pwt,
                                        (float*)p_state, nullptr, BL, HD, HD,
                                        nullptr, nullptr, 0, -1);
    }

    for (int t = 0; t < NLMAX; t++) {
        k_builds_ln<<<BL, 256>>>(t, pw, pb, ln1g, ln1b);
        {
            dim3 gq(QKVN/128, BL/128);
            k_gemm_h<<<gq, 256, SMEM_H>>>((const __half*)p_xnh, (const __half*)p_wqkvt,
                                          nullptr, (__half*)p_qkvh, BL, QKVN, HD,
                                          nullptr, nullptr, 0, t);
        }
        k_attn<<<BB*NHEAD, 256>>>(t);
        {
            dim3 go(HD/128, BL/128);
            k_gemm_h<<<go, 256, SMEM_H>>>((const __half*)p_ctxh, (const __half*)p_wot,
                                          (float*)p_s2, nullptr, BL, HD, HD,
                                          nullptr, (const float*)p_s, 0, t);
        }
        k_ln<<<BL, 256>>>(t, (const float*)p_s2, ln2g, ln2b);
        {
            // conv1: padded A=xn2hp, out midhp (padded), relu
            dim3 gc1(FSZ/128, BL/128);
            k_conv_h<<<gc1, 256, SMEM_C>>>((const __half*)p_xn2hp, (const __half*)p_w1t,
                                           (__half*)p_midhp, FSZ, HD,
                                           c1b, nullptr, 1, t, 0);
        }
        {
            // conv2: padded A=midhp, resid s2, fused halting (writes g_state/g_prev)
            dim3 gc2(HD/128, BL/128);
            k_conv_h<<<gc2, 256, SMEM_C>>>((const __half*)p_midhp, (const __half*)p_w2t,
                                           nullptr, HD, FSZ,
                                           c2b, (const float*)p_s2, 0, t, 1);
        }
    }

    k_pool<<<BB, 256>>>();
    {
        dim3 grid(VOC/128, BB/128);
        k_gemm_h<<<grid, 256, SMEM_H>>>((const __half*)p_pooledh, (const __half*)p_embh,
                                        out, nullptr, BB, VOC, HD,
                                        outb, nullptr, 0, -1);
    }
    k_softmax<<<BB, 1024>>>(out);
    k_tail<<<(BL + 255)/256, 256>>>(out);
}

// round 16
// speedup vs baseline: 1.8535x; 1.0204x over previous
#include <cuda_runtime.h>
#include <cuda_fp16.h>
#include <math.h>
#include <cstdint>

#define BB     256
#define MEMN   70
#define SLENQ  11
#define LQ     71
#define LQP    73
#define PTOT   (BB*LQP)      // 18688
#define BL     (BB*LQ)       // 18176
#define HD     512
#define FSZ    2048
#define NHEAD  8
#define DKH    64
#define NLMAX  6
#define VOC    32000
#define QKVN   1536
#define THRESHV 0.9f
#define EPSV   1e-6f

// GEMM staging
#define ASTRIDE 72
#define STG_BYTES  (128*ASTRIDE*2)         // 18432
#define SMEM_H (3*2*STG_BYTES)             // 110592 (dense)
#define AROWS  134
#define ASTG_C (AROWS*ASTRIDE*2)           // 19296
#define SMEM_C (2*ASTG_C + 3*STG_BYTES)    // 93888 (conv)

// ---------------- scratch (device globals; no allocation) ----------------
__device__ float  g_state[BL*HD];
__device__ float  g_prev[BL*HD];
__device__ float  g_s2[BL*HD];
__device__ __half g_xh[BL*HD];
__device__ __half g_xnh[BL*HD];
__device__ __half g_xn2hp[PTOT*HD];        // padded conv1 input
__device__ __half g_midhp[(long)PTOT*FSZ]; // padded conv2 input
__device__ __half g_qkvh[BL*QKVN];
__device__ __half g_ctxh[BL*HD];
__device__ __half g_pwt[HD*HD];
__device__ __half g_wot[HD*HD];
__device__ __half g_wqkvt[QKVN*HD];
__device__ __half g_w1t[FSZ*3*HD];
__device__ __half g_w2t[HD*3*FSZ];
__device__ __half g_embh[VOC*HD];
__device__ __half g_pooledh[BB*HD];
__device__ float  g_tsig[LQ*HD];
__device__ float  g_psig[NLMAX*HD];
__device__ float  g_hp[BL], g_rem[BL], g_nu[BL], g_uw[BL];
__device__ int    g_act[8];

// ---------------- helpers ----------------
__device__ __forceinline__ uint32_t smem_u32(const void* p) {
    uint32_t a;
    asm("{ .reg .u64 t; cvta.to.shared.u64 t, %1; cvt.u32.u64 %0, t; }" : "=r"(a) : "l"(p));
    return a;
}

__device__ __forceinline__ void mma_f16(float* d, const unsigned* a, const unsigned* b) {
    asm volatile(
        "mma.sync.aligned.m16n8k16.row.col.f32.f16.f16.f32 "
        "{%0,%1,%2,%3}, {%4,%5,%6,%7}, {%8,%9}, {%0,%1,%2,%3};"
        : "+f"(d[0]), "+f"(d[1]), "+f"(d[2]), "+f"(d[3])
        : "r"(a[0]), "r"(a[1]), "r"(a[2]), "r"(a[3]), "r"(b[0]), "r"(b[1]));
}

__device__ __forceinline__ void ldsm4(unsigned& r0, unsigned& r1, unsigned& r2, unsigned& r3,
                                      uint32_t addr) {
    asm volatile("ldmatrix.sync.aligned.m8n8.x4.shared.b16 {%0,%1,%2,%3}, [%4];"
                 : "=r"(r0), "=r"(r1), "=r"(r2), "=r"(r3) : "r"(addr));
}

__device__ __forceinline__ void cp16s(uint32_t daddr, const void* src, int ss) {
    asm volatile("cp.async.cg.shared.global [%0], [%1], 16, %2;"
                 :: "r"(daddr), "l"(src), "r"(ss));
}
__device__ __forceinline__ void cp_commit() { asm volatile("cp.async.commit_group;"); }
__device__ __forceinline__ void cp_wait1()  { asm volatile("cp.async.wait_group 1;"); }

__device__ __forceinline__ float blockReduceSum(float v) {
    __shared__ float sh[32];
    __shared__ float res;
    int lane = threadIdx.x & 31, wid = threadIdx.x >> 5;
#pragma unroll
    for (int o = 16; o; o >>= 1) v += __shfl_xor_sync(0xffffffffu, v, o);
    if (lane == 0) sh[wid] = v;
    __syncthreads();
    if (wid == 0) {
        float x = (lane < (int)(blockDim.x >> 5)) ? sh[lane] : 0.f;
#pragma unroll
        for (int o = 16; o; o >>= 1) x += __shfl_xor_sync(0xffffffffu, x, o);
        if (lane == 0) res = x;
    }
    __syncthreads();
    return res;
}

__device__ __forceinline__ float blockReduceMax(float v) {
    __shared__ float sh[32];
    __shared__ float res;
    int lane = threadIdx.x & 31, wid = threadIdx.x >> 5;
#pragma unroll
    for (int o = 16; o; o >>= 1) v = fmaxf(v, __shfl_xor_sync(0xffffffffu, v, o));
    if (lane == 0) sh[wid] = v;
    __syncthreads();
    if (wid == 0) {
        float x = (lane < (int)(blockDim.x >> 5)) ? sh[lane] : -3.0e38f;
#pragma unroll
        for (int o = 16; o; o >>= 1) x = fmaxf(x, __shfl_xor_sync(0xffffffffu, x, o));
        if (lane == 0) res = x;
    }
    __syncthreads();
    return res;
}

// ---------------- prepA: init + pads + timing signals ----------------
__global__ void k_prepA() {
    int i = blockIdx.x * blockDim.x + threadIdx.x;
    const float log_inc = logf(1e4f) / 255.f;
    if (i < BL*HD) g_prev[i] = 0.f;
    if (i < BL) { g_hp[i] = 0.f; g_rem[i] = 0.f; g_nu[i] = 0.f; }
    if (i < 8) g_act[i] = (i == 0) ? 1 : 0;
    if (i < LQ*HD) {
        int pos = i / HD, c = i % HD;
        int j = (c < 256) ? c : c - 256;
        float val = (float)pos * expf(-log_inc * (float)j);
        g_tsig[i] = (c < 256) ? sinf(val) : cosf(val);
    }
    if (i < NLMAX*HD) {
        int pos = i / HD, c = i % HD;
        int j = (c < 256) ? c : c - 256;
        float val = (float)pos * expf(-log_inc * (float)j);
        g_psig[i] = (c < 256) ? sinf(val) : cosf(val);
    }
    if (i < 512*FSZ) {
        int row = i / FSZ, c = i % FSZ;
        int b = row >> 1, side = row & 1;
        g_midhp[(long)(b*LQP + side*(LQP-1))*FSZ + c] = __float2half_rn(0.f);
    }
    if (i < 512*HD) {
        int row = i / HD, c = i % HD;
        int b = row >> 1, side = row & 1;
        g_xn2hp[(long)(b*LQP + side*(LQP-1))*HD + c] = __float2half_rn(0.f);
    }
}

// ---------------- prepB: all weight conversions ----------------
__global__ void k_prepB(const float* __restrict__ emb, const float* __restrict__ projw,
                        const float* __restrict__ wo, const float* __restrict__ wq,
                        const float* __restrict__ wk, const float* __restrict__ wv,
                        const float* __restrict__ c1w, const float* __restrict__ c2w) {
    long i = (long)blockIdx.x * blockDim.x + threadIdx.x;
    if (i < (long)VOC*HD) g_embh[i] = __float2half_rn(emb[i]);
    if (i < FSZ*3*HD) {
        int n = (int)i / (3*HD), k = (int)i % (3*HD);
        int kk = k / HD, c = k % HD;
        g_w1t[i] = __float2half_rn(c1w[(n*HD + c)*3 + kk]);
    }
    if (i < HD*3*FSZ) {
        int n = (int)i / (3*FSZ), k = (int)i % (3*FSZ);
        int kk = k / FSZ, c = k % FSZ;
        g_w2t[i] = __float2half_rn(c2w[(n*FSZ + c)*3 + kk]);
    }
    if (i < HD*HD) {
        int n = (int)i / HD, k = (int)i % HD;
        g_pwt[i] = __float2half_rn(projw[k*HD + n]);
        g_wot[i] = __float2half_rn(wo[k*HD + n]);
    }
    if (i < QKVN*HD) {
        int n = (int)i / HD, k = (int)i % HD;
        float v;
        if (n < 512)       v = 0.125f * wq[k*HD + n];
        else if (n < 1024) v = wk[k*HD + n - 512];
        else               v = wv[k*HD + n - 1024];
        g_wqkvt[i] = __float2half_rn(v);
    }
}

__global__ void k_embed(const int* __restrict__ story, const int* __restrict__ query,
                        const float* __restrict__ emb, const float* __restrict__ mask) {
    int row = blockIdx.x;
    int b = row / LQ, m = row % LQ;
    for (int c = threadIdx.x; c < HD; c += blockDim.x) {
        float acc = 0.f;
        if (m < MEMN) {
#pragma unroll
            for (int s = 0; s < SLENQ; s++) {
                int tok = story[(b*MEMN + m)*SLENQ + s];
                acc += emb[(long)tok*HD + c] * mask[s*HD + c];
            }
        } else {
#pragma unroll
            for (int s = 0; s < SLENQ; s++) {
                int tok = query[b*SLENQ + s];
                acc += emb[(long)tok*HD + c] * mask[s*HD + c];
            }
        }
        g_xh[row*HD + c] = __float2half_rn(acc);
    }
}

// ============ dense fp16 GEMM: 128x128, K-panel 64, 3-stage, ldmatrix ============
// resid3: residual computed as g_state + tsig + psig(t) (O-proj path).
__global__ void __launch_bounds__(256, 2)
k_gemm_h(const __half* __restrict__ A, const __half* __restrict__ W,
         float* __restrict__ Cf, __half* __restrict__ Ch,
         int M, int N, int K,
         const float* __restrict__ bias, const float* __restrict__ resid,
         int relu, int actidx, int resid3, int t) {
    if (actidx >= 0 && !g_act[actidx]) return;
    extern __shared__ __half sm[];
    const uint32_t As0 = smem_u32(sm);
    const uint32_t Bs0 = As0 + 3*STG_BYTES;

    const int tid = threadIdx.x;
    const int m0 = blockIdx.y * 128;
    const int n0 = blockIdx.x * 128;
    const int lane = tid & 31, wid = tid >> 5;
    const int wm = wid & 3, wn = wid >> 2;
    const int g = lane >> 2, tq = lane & 3;
    const int sect = lane >> 3, lr = lane & 7;

    float acc[2][8][4];
#pragma unroll
    for (int mi = 0; mi < 2; mi++)
#pragma unroll
        for (int ni = 0; ni < 8; ni++)
#pragma unroll
            for (int j = 0; j < 4; j++) acc[mi][ni][j] = 0.f;

    uint32_t a_off[2], b_off[4];
#pragma unroll
    for (int mi = 0; mi < 2; mi++)
        a_off[mi] = (uint32_t)((wm*32 + mi*16 + (sect & 1)*8 + lr)*ASTRIDE + (sect >> 1)*8);
#pragma unroll
    for (int p = 0; p < 4; p++)
        b_off[p] = (uint32_t)((wn*64 + p*16 + (sect >> 1)*8 + lr)*ASTRIDE + (sect & 1)*8);

    const int NP = K >> 6;

    auto loadP = [&](int k0, int buf) {
        uint32_t Ab = As0 + buf*STG_BYTES;
        uint32_t Bb = Bs0 + buf*STG_BYTES;
#pragma unroll
        for (int i = 0; i < 4; i++) {
            int id = tid + i*256;
            int row = id >> 3, ch = (id & 7)*8;
            cp16s(Ab + (uint32_t)(row*ASTRIDE + ch)*2,
                  &A[(long)(m0 + row)*K + k0 + ch], 16);
        }
#pragma unroll
        for (int i = 0; i < 4; i++) {
            int id = tid + i*256;
            int row = id >> 3, ch = (id & 7)*8;
            cp16s(Bb + (uint32_t)(row*ASTRIDE + ch)*2,
                  &W[(long)(n0 + row)*K + k0 + ch], 16);
        }
    };

    auto compute = [&](int buf) {
        uint32_t Ab = As0 + buf*STG_BYTES;
        uint32_t Bb = Bs0 + buf*STG_BYTES;
#pragma unroll
        for (int ks = 0; ks < 4; ks++) {
            int kk = ks*16;
            unsigned a[2][4], b[8][2];
#pragma unroll
            for (int mi = 0; mi < 2; mi++)
                ldsm4(a[mi][0], a[mi][1], a[mi][2], a[mi][3], Ab + (a_off[mi] + kk)*2);
#pragma unroll
            for (int p = 0; p < 4; p++) {
                unsigned r0, r1, r2, r3;
                ldsm4(r0, r1, r2, r3, Bb + (b_off[p] + kk)*2);
                b[2*p][0] = r0; b[2*p][1] = r1;
                b[2*p+1][0] = r2; b[2*p+1][1] = r3;
            }
#pragma unroll
            for (int mi = 0; mi < 2; mi++)
#pragma unroll
                for (int ni = 0; ni < 8; ni++)
                    mma_f16(acc[mi][ni], a[mi], b[ni]);
        }
    };

    loadP(0, 0);
    cp_commit();
    if (NP > 1) loadP(64, 1);
    cp_commit();

    for (int p = 0; p < NP; p++) {
        cp_wait1();
        __syncthreads();
        int pn = p + 2;
        if (pn < NP) loadP(pn << 6, pn % 3);
        cp_commit();
        compute(p % 3);
    }

#pragma unroll
    for (int mi = 0; mi < 2; mi++) {
        int r0 = m0 + wm*32 + mi*16 + g;
        int l0 = r0 % LQ, l1 = (r0 + 8) % LQ;
#pragma unroll
        for (int ni = 0; ni < 8; ni++) {
            int c0 = n0 + wn*64 + ni*8 + 2*tq;
            float b0 = bias ? bias[c0] : 0.f;
            float b1 = bias ? bias[c0 + 1] : 0.f;
            float v0 = acc[mi][ni][0] + b0;
            float v1 = acc[mi][ni][1] + b1;
            float v2 = acc[mi][ni][2] + b0;
            float v3 = acc[mi][ni][3] + b1;
            if (resid3) {
                v0 += g_state[(long)r0*N + c0]       + g_tsig[l0*HD + c0]     + g_psig[t*HD + c0];
                v1 += g_state[(long)r0*N + c0 + 1]   + g_tsig[l0*HD + c0 + 1] + g_psig[t*HD + c0 + 1];
                v2 += g_state[(long)(r0+8)*N + c0]   + g_tsig[l1*HD + c0]     + g_psig[t*HD + c0];
                v3 += g_state[(long)(r0+8)*N + c0+1] + g_tsig[l1*HD + c0 + 1] + g_psig[t*HD + c0 + 1];
            } else if (resid) {
                v0 += resid[(long)r0*N + c0];
                v1 += resid[(long)r0*N + c0 + 1];
                v2 += resid[(long)(r0 + 8)*N + c0];
                v3 += resid[(long)(r0 + 8)*N + c0 + 1];
            }
            if (relu) {
                v0 = fmaxf(v0, 0.f); v1 = fmaxf(v1, 0.f);
                v2 = fmaxf(v2, 0.f); v3 = fmaxf(v3, 0.f);
            }
            if (Cf) {
                Cf[(long)r0*N + c0]           = v0;
                Cf[(long)r0*N + c0 + 1]       = v1;
                Cf[(long)(r0 + 8)*N + c0]     = v2;
                Cf[(long)(r0 + 8)*N + c0 + 1] = v3;
            } else {
                __half2 h01 = __floats2half2_rn(v0, v1);
                __half2 h23 = __floats2half2_rn(v2, v3);
                *(__half2*)&Ch[(long)r0*N + c0]       = h01;
                *(__half2*)&Ch[(long)(r0 + 8)*N + c0] = h23;
            }
        }
    }
}

// ============ conv fp16 GEMM over padded input (A shared across 3 taps) ============
__global__ void __launch_bounds__(256, 2)
k_conv_h(const __half* __restrict__ A, const __half* __restrict__ W,
         __half* __restrict__ Chp, int N, int Cin,
         const float* __restrict__ bias, const float* __restrict__ resid,
         int relu, int actidx, int haltfuse) {
    if (!g_act[actidx]) return;
    extern __shared__ __half sm[];
    const uint32_t As0 = smem_u32(sm);
    const uint32_t Bs0 = As0 + 2*ASTG_C;

    const int tid = threadIdx.x;
    const int m0 = blockIdx.y * 128;
    const int n0 = blockIdx.x * 128;
    const int lane = tid & 31, wid = tid >> 5;
    const int wm = wid & 3, wn = wid >> 2;
    const int g = lane >> 2, tq = lane & 3;
    const int sect = lane >> 3, lr = lane & 7;
    const int Kfull = 3*Cin;

    float acc[2][8][4];
#pragma unroll
    for (int mi = 0; mi < 2; mi++)
#pragma unroll
        for (int ni = 0; ni < 8; ni++)
#pragma unroll
            for (int j = 0; j < 4; j++) acc[mi][ni][j] = 0.f;

    const int b0 = m0 / LQ;
    const int pw0 = b0*LQP + (m0 - b0*LQ);

    int prel[2];
#pragma unroll
    for (int mi = 0; mi < 2; mi++) {
        int rowm = m0 + wm*32 + mi*16 + (sect & 1)*8 + lr;
        int bb = rowm / LQ;
        prel[mi] = bb*LQP + (rowm - bb*LQ) - pw0;
    }
    const int acol = (sect >> 1)*8;

    uint32_t b_off[4];
#pragma unroll
    for (int p = 0; p < 4; p++)
        b_off[p] = (uint32_t)((wn*64 + p*16 + (sect >> 1)*8 + lr)*ASTRIDE + (sect & 1)*8);

    const int ncp = Cin >> 6;
    const int NV = 3*ncp;

    auto loadA = [&](int c, int buf) {
        uint32_t Ab = As0 + buf*ASTG_C;
        int cb = c*64;
        for (int i = tid; i < AROWS*8; i += 256) {
            int row = i >> 3, ch = (i & 7)*8;
            int gidx = pw0 + row;
            int ok = (gidx < PTOT);
            cp16s(Ab + (uint32_t)(row*ASTRIDE + ch)*2,
                  &A[(long)(ok ? gidx : 0)*Cin + cb + ch], ok ? 16 : 0);
        }
    };

    auto loadB = [&](int v, int buf) {
        uint32_t Bb = Bs0 + buf*STG_BYTES;
        int kk = v % 3, c = v / 3;
        int kcol = kk*Cin + c*64;
#pragma unroll
        for (int i = 0; i < 4; i++) {
            int id = tid + i*256;
            int row = id >> 3, ch = (id & 7)*8;
            cp16s(Bb + (uint32_t)(row*ASTRIDE + ch)*2,
                  &W[(long)(n0 + row)*Kfull + kcol + ch], 16);
        }
    };

    auto compute = [&](int v) {
        int kk = v % 3;
        uint32_t Ab = As0 + ((v/3) & 1)*ASTG_C;
        uint32_t Bb = Bs0 + (v % 3)*STG_BYTES;
#pragma unroll
        for (int ks = 0; ks < 4; ks++) {
            int kc = ks*16;
            unsigned a[2][4], b[8][2];
#pragma unroll
            for (int mi = 0; mi < 2; mi++)
                ldsm4(a[mi][0], a[mi][1], a[mi][2], a[mi][3],
                      Ab + (uint32_t)((prel[mi] + kk)*ASTRIDE + acol + kc)*2);
#pragma unroll
            for (int p = 0; p < 4; p++) {
                unsigned r0, r1, r2, r3;
                ldsm4(r0, r1, r2, r3, Bb + (b_off[p] + kc)*2);
                b[2*p][0] = r0; b[2*p][1] = r1;
                b[2*p+1][0] = r2; b[2*p+1][1] = r3;
            }
#pragma unroll
            for (int mi = 0; mi < 2; mi++)
#pragma unroll
                for (int ni = 0; ni < 8; ni++)
                    mma_f16(acc[mi][ni], a[mi], b[ni]);
        }
    };

    loadA(0, 0);
    loadB(0, 0);
    cp_commit();
    if (NV > 1) loadB(1, 1);
    cp_commit();

    for (int v = 0; v < NV; v++) {
        cp_wait1();
        __syncthreads();
        int vv = v + 2;
        if (vv < NV) {
            loadB(vv, vv % 3);
            if (vv % 3 == 2) {
                int c = (vv + 1)/3;
                if (c < ncp) loadA(c, c & 1);
            }
        }
        cp_commit();
        compute(v);
    }

#pragma unroll
    for (int mi = 0; mi < 2; mi++) {
        int r0 = m0 + wm*32 + mi*16 + g;
        float uw0 = 0.f, uw1 = 0.f;
        if (haltfuse) { uw0 = g_uw[r0]; uw1 = g_uw[r0 + 8]; }
#pragma unroll
        for (int ni = 0; ni < 8; ni++) {
            int c0 = n0 + wn*64 + ni*8 + 2*tq;
            float b0 = bias[c0], b1 = bias[c0 + 1];
            float v0 = acc[mi][ni][0] + b0;
            float v1 = acc[mi][ni][1] + b1;
            float v2 = acc[mi][ni][2] + b0;
            float v3 = acc[mi][ni][3] + b1;
            if (resid) {
                v0 += resid[(long)r0*N + c0];
                v1 += resid[(long)r0*N + c0 + 1];
                v2 += resid[(long)(r0 + 8)*N + c0];
                v3 += resid[(long)(r0 + 8)*N + c0 + 1];
            }
            if (relu) {
                v0 = fmaxf(v0, 0.f); v1 = fmaxf(v1, 0.f);
                v2 = fmaxf(v2, 0.f); v3 = fmaxf(v3, 0.f);
            }
            if (haltfuse) {
                long i00 = (long)r0*N + c0;
                long i10 = (long)(r0 + 8)*N + c0;
                g_state[i00]     = v0;
                g_state[i00 + 1] = v1;
                g_state[i10]     = v2;
                g_state[i10 + 1] = v3;
                g_prev[i00]     = v0*uw0 + g_prev[i00]*(1.f - uw0);
                g_prev[i00 + 1] = v1*uw0 + g_prev[i00 + 1]*(1.f - uw0);
                g_prev[i10]     = v2*uw1 + g_prev[i10]*(1.f - uw1);
                g_prev[i10 + 1] = v3*uw1 + g_prev[i10 + 1]*(1.f - uw1);
            } else {
                int ba = r0 / LQ, bb = (r0 + 8) / LQ;
                long p0 = (long)(ba*LQP + 1 + (r0 - ba*LQ))*N + c0;
                long p1 = (long)(bb*LQP + 1 + (r0 + 8 - bb*LQ))*N + c0;
                __half2 h01 = __floats2half2_rn(v0, v1);
                __half2 h23 = __floats2half2_rn(v2, v3);
                *(__half2*)&Chp[p0] = h01;
                *(__half2*)&Chp[p1] = h23;
            }
        }
    }
}

// ---------------- ACT step pieces ----------------
__global__ void k_builds_ln(int t, const float* __restrict__ pw, const float* __restrict__ pb,
                            const float* __restrict__ lng, const float* __restrict__ lnb) {
    if (!g_act[t]) return;
    int c0 = threadIdx.x, c1 = threadIdx.x + 256;
    for (int row = blockIdx.x; row < BL; row += 2048) {
        int l = row % LQ;
        float v0 = g_state[row*HD + c0] + g_tsig[l*HD + c0] + g_psig[t*HD + c0];
        float v1 = g_state[row*HD + c1] + g_tsig[l*HD + c1] + g_psig[t*HD + c1];
        float dot = v0*pw[c0] + v1*pw[c1];
        float tot = blockReduceSum(dot);
        if (threadIdx.x == 0) {
            float pr = 1.f / (1.f + expf(-(tot + pb[0])));
            float hp = g_hp[row], rem = g_rem[row], nu = g_nu[row];
            float still = (hp < 1.0f) ? 1.f : 0.f;
            float tt = hp + pr*still;
            float nh  = ((tt > THRESHV) ? 1.f : 0.f)*still;
            float st2 = ((tt <= THRESHV) ? 1.f : 0.f)*still;
            float hp2 = hp + pr*st2;
            float rem2 = rem + nh*(1.f - hp2);
            hp2 = hp2 + nh*rem2;
            float nu2 = nu + st2 + nh;
            float uw = pr*st2 + nh*rem2;
            g_hp[row] = hp2; g_rem[row] = rem2; g_nu[row] = nu2; g_uw[row] = uw;
            if (hp2 < THRESHV && nu2 < (float)NLMAX) g_act[t + 1] = 1;
        }
        float mu = blockReduceSum(v0 + v1) / (float)HD;
        float d0 = v0 - mu, d1 = v1 - mu;
        float var = blockReduceSum(d0*d0 + d1*d1) / (float)(HD - 1);
        float inv = 1.f / (sqrtf(var) + EPSV);
        g_xnh[row*HD + c0] = __float2half_rn(lng[c0]*d0*inv + lnb[c0]);
        g_xnh[row*HD + c1] = __float2half_rn(lng[c1]*d1*inv + lnb[c1]);
    }
}

__global__ void k_ln(int t, const float* __restrict__ X, const float* __restrict__ g,
                     const float* __restrict__ b) {
    if (!g_act[t]) return;
    int c0 = threadIdx.x, c1 = threadIdx.x + 256;
    for (int row = blockIdx.x; row < BL; row += 2048) {
        int bb = row / LQ;
        long prow = (long)(bb*LQP + 1 + (row - bb*LQ));
        const float* x = X + row*HD;
        float x0 = x[c0], x1 = x[c1];
        float mu = blockReduceSum(x0 + x1) / (float)HD;
        float d0 = x0 - mu, d1 = x1 - mu;
        float var = blockReduceSum(d0*d0 + d1*d1) / (float)(HD - 1);
        float inv = 1.f / (sqrtf(var) + EPSV);
        g_xn2hp[prow*HD + c0] = __float2half_rn(g[c0]*d0*inv + b[c0]);
        g_xn2hp[prow*HD + c1] = __float2half_rn(g[c1]*d1*inv + b[c1]);
    }
}

#define KVS 68
__global__ void k_attn(int t) {
    if (!g_act[t]) return;
    int bh = blockIdx.x;
    int b = bh / NHEAD, h = bh % NHEAD;
    __shared__ float ks[LQ*KVS];
    __shared__ float vs[LQ*KVS];
    __shared__ float qrow[8][DKH];
    __shared__ float ps[8][72];
    int tid = threadIdx.x;
    long qbase = (long)(b*LQ)*QKVN + h*DKH;
    for (int i = tid; i < LQ*(DKH/2); i += 256) {
        int j = i / (DKH/2), d2 = (i % (DKH/2))*2;
        float2 kf = __half22float2(*(const __half2*)&g_qkvh[qbase + 512 + (long)j*QKVN + d2]);
        float2 vf = __half22float2(*(const __half2*)&g_qkvh[qbase + 1024 + (long)j*QKVN + d2]);
        ks[j*KVS + d2] = kf.x; ks[j*KVS + d2 + 1] = kf.y;
        vs[j*KVS + d2] = vf.x; vs[j*KVS + d2 + 1] = vf.y;
    }
    __syncthreads();
    int w = tid >> 5, lane = tid & 31;
    long ctxbase = (long)(b*LQ)*HD + h*DKH;
    for (int r = w; r < LQ; r += 8) {
        for (int d = lane; d < DKH; d += 32)
            qrow[w][d] = __half2float(g_qkvh[qbase + (long)r*QKVN + d]);
        __syncwarp();
        float sc[3];
#pragma unroll
        for (int jj = 0; jj < 3; jj++) {
            int j = lane + jj*32;
            float a = -3.0e38f;
            if (j < LQ) {
                a = 0.f;
#pragma unroll
                for (int d4 = 0; d4 < DKH; d4 += 4) {
                    float4 q4 = *(const float4*)&qrow[w][d4];
                    float4 k4 = *(const float4*)&ks[j*KVS + d4];
                    a += q4.x*k4.x; a += q4.y*k4.y;
                    a += q4.z*k4.z; a += q4.w*k4.w;
                }
            }
            sc[jj] = a;
        }
        float mx = fmaxf(sc[0], fmaxf(sc[1], sc[2]));
#pragma unroll
        for (int o = 16; o; o >>= 1) mx = fmaxf(mx, __shfl_xor_sync(0xffffffffu, mx, o));
        float sum = 0.f;
#pragma unroll
        for (int jj = 0; jj < 3; jj++) {
            int j = lane + jj*32;
            float e = (j < LQ) ? expf(sc[jj] - mx) : 0.f;
            sc[jj] = e; sum += e;
        }
#pragma unroll
        for (int o = 16; o; o >>= 1) sum += __shfl_xor_sync(0xffffffffu, sum, o);
        float inv = 1.f / sum;
#pragma unroll
        for (int jj = 0; jj < 3; jj++) {
            int j = lane + jj*32;
            if (j < LQ) ps[w][j] = sc[jj]*inv;
        }
        __syncwarp();
        {
            int d = lane*2;
            float ax = 0.f, ay = 0.f;
#pragma unroll 8
            for (int j = 0; j < LQ; j++) {
                float wp = ps[w][j];
                float2 v2 = *(const float2*)&vs[j*KVS + d];
                ax += wp*v2.x; ay += wp*v2.y;
            }
            *(__half2*)&g_ctxh[ctxbase + (long)r*HD + d] = __floats2half2_rn(ax, ay);
        }
        __syncwarp();
    }
}

// ---------------- pooling+tail / softmax ----------------
__global__ void k_pooltail(float* __restrict__ out) {
    int b = blockIdx.x;
    for (int c = threadIdx.x; c < HD; c += blockDim.x) {
        float a = 0.f;
        for (int l = 0; l < LQ; l++) a += g_prev[(b*LQ + l)*HD + c];
        g_pooledh[b*HD + c] = __float2half_rn(a / (float)LQ);
    }
    for (int l = threadIdx.x; l < LQ; l += blockDim.x) {
        int i = b*LQ + l;
        out[(long)2*BB*VOC + i]      = g_rem[i];
        out[(long)2*BB*VOC + BL + i] = g_nu[i];
    }
}

__global__ void k_softmax(float* __restrict__ out) {
    int b = blockIdx.x;
    const float* a = out + (long)b*VOC;
    float* sm = out + (long)BB*VOC + (long)b*VOC;
    float mx = -3.0e38f;
    for (int i = threadIdx.x; i < VOC; i += blockDim.x) mx = fmaxf(mx, a[i]);
    float M = blockReduceMax(mx);
    float s = 0.f;
    for (int i = threadIdx.x; i < VOC; i += blockDim.x) s += expf(a[i] - M);
    float S = blockReduceSum(s);
    float inv = 1.f / S;
    for (int i = threadIdx.x; i < VOC; i += blockDim.x) sm[i] = expf(a[i] - M)*inv;
}

// ---------------- host ----------------
extern "C" void kernel_launch(void* const* d_in, const int* in_sizes, int n_in,
                              void* d_out, int out_size) {
    const int*   story = (const int*)d_in[0];
    const int*   query = (const int*)d_in[1];
    const float* emb   = (const float*)d_in[2];
    const float* mask  = (const float*)d_in[3];
    const float* projw = (const float*)d_in[4];
    const float* ln1g  = (const float*)d_in[5];
    const float* ln1b  = (const float*)d_in[6];
    const float* wq    = (const float*)d_in[7];
    const float* wk    = (const float*)d_in[8];
    const float* wv    = (const float*)d_in[9];
    const float* wo    = (const float*)d_in[10];
    const float* c1w   = (const float*)d_in[11];
    const float* c1b   = (const float*)d_in[12];
    const float* c2w   = (const float*)d_in[13];
    const float* c2b   = (const float*)d_in[14];
    const float* ln2g  = (const float*)d_in[15];
    const float* ln2b  = (const float*)d_in[16];
    const float* pw    = (const float*)d_in[17];
    const float* pb    = (const float*)d_in[18];
    const float* outb  = (const float*)d_in[19];
    float* out = (float*)d_out;

    void *p_state, *p_s2, *p_xh, *p_xnh, *p_xn2hp, *p_qkvh, *p_ctxh,
         *p_midhp, *p_pwt, *p_wot, *p_wqkvt, *p_w1t, *p_w2t, *p_embh, *p_pooledh;
    cudaGetSymbolAddress(&p_state, g_state);
    cudaGetSymbolAddress(&p_s2, g_s2);
    cudaGetSymbolAddress(&p_xh, g_xh);
    cudaGetSymbolAddress(&p_xnh, g_xnh);
    cudaGetSymbolAddress(&p_xn2hp, g_xn2hp);
    cudaGetSymbolAddress(&p_qkvh, g_qkvh);
    cudaGetSymbolAddress(&p_ctxh, g_ctxh);
    cudaGetSymbolAddress(&p_midhp, g_midhp);
    cudaGetSymbolAddress(&p_pwt, g_pwt);
    cudaGetSymbolAddress(&p_wot, g_wot);
    cudaGetSymbolAddress(&p_wqkvt, g_wqkvt);
    cudaGetSymbolAddress(&p_w1t, g_w1t);
    cudaGetSymbolAddress(&p_w2t, g_w2t);
    cudaGetSymbolAddress(&p_embh, g_embh);
    cudaGetSymbolAddress(&p_pooledh, g_pooledh);

    cudaFuncSetAttribute(k_gemm_h, cudaFuncAttributeMaxDynamicSharedMemorySize, SMEM_H);
    cudaFuncSetAttribute(k_conv_h, cudaFuncAttributeMaxDynamicSharedMemorySize, SMEM_C);

    // launch order: ncu (-s 5 -c 1) profiles launch #6 = first QKV GEMM
    k_prepA<<<(BL*HD + 255)/256, 256>>>();                                            // 1
    k_prepB<<<(int)(((long)VOC*HD + 255)/256), 256>>>(emb, projw, wo, wq, wk, wv,
                                                      c1w, c2w);                      // 2
    k_embed<<<BL, 128>>>(story, query, emb, mask);                                    // 3
    {
        dim3 grid(HD/128, BL/128);                                                    // 4
        k_gemm_h<<<grid, 256, SMEM_H>>>((const __half*)p_xh, (const __half*)p_pwt,
                                        (float*)p_state, nullptr, BL, HD, HD,
                                        nullptr, nullptr, 0, -1, 0, 0);
    }

    for (int t = 0; t < NLMAX; t++) {
        k_builds_ln<<<2048, 256>>>(t, pw, pb, ln1g, ln1b);                            // 5
        {
            dim3 gq(QKVN/128, BL/128);                                                // 6 <- profiled
            k_gemm_h<<<gq, 256, SMEM_H>>>((const __half*)p_xnh, (const __half*)p_wqkvt,
                                          nullptr, (__half*)p_qkvh, BL, QKVN, HD,
                                          nullptr, nullptr, 0, t, 0, 0);
        }
        k_attn<<<BB*NHEAD, 256>>>(t);
        {
            dim3 go(HD/128, BL/128);
            k_gemm_h<<<go, 256, SMEM_H>>>((const __half*)p_ctxh, (const __half*)p_wot,
                                          (float*)p_s2, nullptr, BL, HD, HD,
                                          nullptr, nullptr, 0, t, 1, t);
        }
        k_ln<<<2048, 256>>>(t, (const float*)p_s2, ln2g, ln2b);
        {
            dim3 gc1(FSZ/128, BL/128);
            k_conv_h<<<gc1, 256, SMEM_C>>>((const __half*)p_xn2hp, (const __half*)p_w1t,
                                           (__half*)p_midhp, FSZ, HD,
                                           c1b, nullptr, 1, t, 0);
        }
        {
            dim3 gc2(HD/128, BL/128);
            k_conv_h<<<gc2, 256, SMEM_C>>>((const __half*)p_midhp, (const __half*)p_w2t,
                                           nullptr, HD, FSZ,
                                           c2b, (const float*)p_s2, 0, t, 1);
        }
    }

    k_pooltail<<<BB, 256>>>(out);
    {
        dim3 grid(VOC/128, BB/128);
        k_gemm_h<<<grid, 256, SMEM_H>>>((const __half*)p_pooledh, (const __half*)p_embh,
                                        out, nullptr, BB, VOC, HD,
                                        outb, nullptr, 0, -1, 0, 0);
    }
    k_softmax<<<BB, 1024>>>(out);
}